// round 12
// baseline (speedup 1.0000x reference)
#include <cuda_runtime.h>
#include <math.h>
#include <stdint.h>

#define NN 5000
#define NE 100000
#define MULC 128

// ---------------- device scratch (static, no allocation) ----------------
__device__ float  g_x[NN * MULC];
__device__ float  g_Meff[16 * 256];
__device__ int    g_cnt[NN];
__device__ int    g_cur[NN];
__device__ int    g_off[NN + 1];
__device__ int    g_perm[NE];
__device__ float  g_A[(size_t)NE * MULC * 4];
__device__ float  g_gate[(size_t)NE * MULC];
__device__ float  g_wm1x[(size_t)NE * MULC];
__device__ float  g_mmsh3[NE * 3];
__device__ float  g_dens[NE];
__device__ float  g_msglin[NN * MULC * 16];
__device__ float  g_mmlin[NN * MULC * 4];
__device__ float2 g_Wp[4 * 128 * 5 * 128];   // Wsk z-paired: ((l*128+uu)*5+zp)*128+v
__device__ float2 g_Wmp[2 * 128 * 5 * 128];  // Wmsk l=0,1 z-paired

__device__ __forceinline__ float silu_f(float x) { return x / (1.0f + __expf(-x)); }
__device__ __forceinline__ float2 f2(float a, float b) { return make_float2(a, b); }
__device__ __forceinline__ float2 make2(float x) { return make_float2(x, x); }
__device__ __forceinline__ float2 ffma2(float2 a, float2 b, float2 c) {
    unsigned long long ra = *reinterpret_cast<unsigned long long*>(&a);
    unsigned long long rb = *reinterpret_cast<unsigned long long*>(&b);
    unsigned long long rc = *reinterpret_cast<unsigned long long*>(&c);
    unsigned long long rd;
    asm("fma.rn.f32x2 %0, %1, %2, %3;" : "=l"(rd) : "l"(ra), "l"(rb), "l"(rc));
    return *reinterpret_cast<float2*>(&rd);
}

// ---------------- launch 1: x = nf@Wup/sqrt(128) + receiver histogram + weight z-pair pack ----
__global__ void __launch_bounds__(128) k_hx(const float* __restrict__ nf,
                                            const float* __restrict__ Wup,
                                            const int* __restrict__ ei,
                                            const float* __restrict__ Wsk,
                                            const float* __restrict__ Wmsk) {
    __shared__ float s[128];
    int n = blockIdx.x, t = threadIdx.x;
    s[t] = nf[n * 128 + t];
    __syncthreads();
    float acc = 0.f;
#pragma unroll 8
    for (int u = 0; u < 128; u++) acc += s[u] * Wup[u * 128 + t];
    g_x[n * 128 + t] = acc * 0.08838834764831845f;
    int gid = n * 128 + t;
    if (gid < NE) atomicAdd(&g_cnt[ei[NE + gid]], 1);
    const int T1 = 4 * 128 * 5 * 128;
    const int T2 = 2 * 128 * 5 * 128;
    if (gid < T1) {
        int v = gid & 127;
        int zp = (gid >> 7) % 5;
        int lu = gid / (5 * 128);
        const float* b = Wsk + ((size_t)lu * 10 + 2 * zp) * 128 + v;
        g_Wp[gid] = f2(b[0], b[128]);
    } else if (gid < T1 + T2) {
        int j = gid - T1;
        int v = j & 127;
        int zp = (j >> 7) % 5;
        int lu = j / (5 * 128);
        const float* b = Wmsk + ((size_t)lu * 10 + 2 * zp) * 128 + v;
        g_Wmp[j] = f2(b[0], b[128]);
    }
}

// ---------------- launch 2: Meff + CSR scan + self-restore zeroing (1 block) ----------------
__global__ void __launch_bounds__(1024) k_scanmeff(
    const float* __restrict__ M1, const float* __restrict__ M2,
    const float* __restrict__ M3, const float* __restrict__ M4) {
    __shared__ float T1[16 * 64];
    __shared__ float T2[16 * 64];
    __shared__ int   s[1024];
    int t = threadIdx.x;
    for (int idx = t; idx < 16 * 64; idx += 1024) {
        int a = idx >> 6, k = idx & 63;
        float acc = 0.f;
        for (int b = 0; b < 64; b++) acc += M1[a * 64 + b] * M2[b * 64 + k];
        T1[idx] = acc;
    }
    __syncthreads();
    for (int idx = t; idx < 16 * 64; idx += 1024) {
        int a = idx >> 6, k = idx & 63;
        float acc = 0.f;
        for (int b = 0; b < 64; b++) acc += T1[a * 64 + b] * M3[b * 64 + k];
        T2[idx] = acc;
    }
    __syncthreads();
    for (int idx = t; idx < 16 * 256; idx += 1024) {
        int a = idx >> 8, c = idx & 255;
        float acc = 0.f;
        for (int b = 0; b < 64; b++) acc += T2[a * 64 + b] * M4[b * 256 + c];
        g_Meff[idx] = acc * 4.8828125e-4f;
    }
    int carry = 0;
    for (int base = 0; base < NN; base += 1024) {
        int i = base + t;
        int c = (i < NN) ? g_cnt[i] : 0;
        s[t] = c;
        __syncthreads();
        for (int d = 1; d < 1024; d <<= 1) {
            int v = (t >= d) ? s[t - d] : 0;
            __syncthreads();
            s[t] += v;
            __syncthreads();
        }
        if (i < NN) g_off[i] = carry + s[t] - c;
        carry += s[1023];
        __syncthreads();
    }
    if (t == 0) g_off[NN] = NE;
    __syncthreads();
    for (int i = t; i < NN; i += 1024) { g_cnt[i] = 0; g_cur[i] = 0; }
}

// ---------------- launch 3: scatter edges into CSR order ----------------
__global__ void __launch_bounds__(256) k_scatter(const int* __restrict__ ei) {
    int e = blockIdx.x * blockDim.x + threadIdx.x;
    if (e < NE) {
        int r = ei[NE + e];
        int k = atomicAdd(&g_cur[r], 1);
        g_perm[g_off[r] + k] = e;
    }
}

// ---------------- launch 4: edge kernel; layers now edge-pair FFMA2, single pass ----------------
__global__ void __launch_bounds__(256) k_edge(
    const float* __restrict__ W1, const float* __restrict__ W2,
    const float* __restrict__ W3, const float* __restrict__ W4,
    const float* __restrict__ ea, const float* __restrict__ ef,
    const float* __restrict__ mmi, const float* __restrict__ mma,
    const float* __restrict__ Wd, const int* __restrict__ ei)
{
    __shared__ float s_efT[16][8];     // [j][el]
    __shared__ float s_h1T[64][12];    // [j][el], pad 12 (16B-aligned rows)
    __shared__ float s_h2T[64][12];
    __shared__ float s_h3T[64][12];
    __shared__ float s_w4[8][512];
    __shared__ float s_wmm[8][256];
    __shared__ int   s_e[8], s_send[8];
    __shared__ float s_sh0[8], s_mm0[8];

    int t = threadIdx.x;
    int p0 = blockIdx.x * 8;

    if (t < 8) {
        int e = g_perm[p0 + t];
        s_e[t] = e;
        s_send[t] = ei[e];
    }
    __syncthreads();
    if (t < 128) {
        int el = t >> 4, j = t & 15;
        int e = s_e[el], sd = s_send[el];
        s_efT[j][el] = (j < 8) ? ef[e * 8 + j] : mmi[sd * 8 + (j - 8)];
    }
    __syncthreads();

    int i = t & 63;    // output neuron
    int ep = t >> 6;   // edge-pair 0..3
    // layer1: h1 = silu(ef @ W1 / 4), two edges per thread via ffma2
    {
        float2 a = make_float2(0.f, 0.f);
#pragma unroll
        for (int j = 0; j < 16; j++)
            a = ffma2(*(const float2*)&s_efT[j][2 * ep], make2(W1[j * 64 + i]), a);
        *(float2*)&s_h1T[i][2 * ep] = f2(silu_f(a.x * 0.25f), silu_f(a.y * 0.25f));
    }
    __syncthreads();
    // layer2
    {
        float2 a = make_float2(0.f, 0.f);
#pragma unroll 8
        for (int j = 0; j < 64; j++)
            a = ffma2(*(const float2*)&s_h1T[j][2 * ep], make2(W2[j * 64 + i]), a);
        *(float2*)&s_h2T[i][2 * ep] = f2(silu_f(a.x * 0.125f), silu_f(a.y * 0.125f));
    }
    __syncthreads();
    // layer3
    {
        float2 a = make_float2(0.f, 0.f);
#pragma unroll 8
        for (int j = 0; j < 64; j++)
            a = ffma2(*(const float2*)&s_h2T[j][2 * ep], make2(W3[j * 64 + i]), a);
        *(float2*)&s_h3T[i][2 * ep] = f2(silu_f(a.x * 0.125f), silu_f(a.y * 0.125f));
    }
    __syncthreads();
    // w4 = h3 @ W4 / 8 : thread owns cols 2t,2t+1; FFMA2 over edge pairs
    {
        float2 a0[4], a1[4];
#pragma unroll
        for (int p = 0; p < 4; p++) { a0[p] = make_float2(0.f, 0.f); a1[p] = make_float2(0.f, 0.f); }
#pragma unroll 4
        for (int j = 0; j < 64; j++) {
            float2 w = *(const float2*)&W4[j * 512 + 2 * t];
            float4 h0 = *(const float4*)&s_h3T[j][0];
            float4 h1 = *(const float4*)&s_h3T[j][4];
            float2 hp0 = f2(h0.x, h0.y), hp1 = f2(h0.z, h0.w);
            float2 hp2 = f2(h1.x, h1.y), hp3 = f2(h1.z, h1.w);
            float2 w0 = make2(w.x), w1 = make2(w.y);
            a0[0] = ffma2(hp0, w0, a0[0]); a1[0] = ffma2(hp0, w1, a1[0]);
            a0[1] = ffma2(hp1, w0, a0[1]); a1[1] = ffma2(hp1, w1, a1[1]);
            a0[2] = ffma2(hp2, w0, a0[2]); a1[2] = ffma2(hp2, w1, a1[2]);
            a0[3] = ffma2(hp3, w0, a0[3]); a1[3] = ffma2(hp3, w1, a1[3]);
        }
#pragma unroll
        for (int p = 0; p < 4; p++) {
            s_w4[2 * p][2 * t]         = a0[p].x * 0.125f;
            s_w4[2 * p + 1][2 * t]     = a0[p].y * 0.125f;
            s_w4[2 * p][2 * t + 1]     = a1[p].x * 0.125f;
            s_w4[2 * p + 1][2 * t + 1] = a1[p].y * 0.125f;
        }
    }
    // w_mm = ef_mm @ M_eff, FFMA2 over edge pairs
    {
        float2 ac[4];
#pragma unroll
        for (int p = 0; p < 4; p++) ac[p] = make_float2(0.f, 0.f);
#pragma unroll
        for (int j = 0; j < 16; j++) {
            float2 m = make2(g_Meff[j * 256 + t]);
            float4 e0 = *(const float4*)&s_efT[j][0];
            float4 e1 = *(const float4*)&s_efT[j][4];
            ac[0] = ffma2(f2(e0.x, e0.y), m, ac[0]);
            ac[1] = ffma2(f2(e0.z, e0.w), m, ac[1]);
            ac[2] = ffma2(f2(e1.x, e1.y), m, ac[2]);
            ac[3] = ffma2(f2(e1.z, e1.w), m, ac[3]);
        }
#pragma unroll
        for (int p = 0; p < 4; p++) {
            s_wmm[2 * p][t]     = ac[p].x;
            s_wmm[2 * p + 1][t] = ac[p].y;
        }
    }
    if (t < 8) {
        int el = t;
        int e = s_e[el], sd = s_send[el];
        s_sh0[el] = ea[(size_t)e * 16];
        float q = 0.f;
#pragma unroll
        for (int j = 0; j < 8; j++) q += ef[e * 8 + j] * Wd[j];
        q *= 0.35355339059327373f;
        g_dens[p0 + el] = tanhf(q * q);
        s_mm0[el] = mma[sd * 4];
        g_mmsh3[(p0 + el) * 3 + 0] = mma[sd * 4 + 1];
        g_mmsh3[(p0 + el) * 3 + 1] = mma[sd * 4 + 2];
        g_mmsh3[(p0 + el) * 3 + 2] = mma[sd * 4 + 3];
    }
    __syncthreads();
#pragma unroll
    for (int r = 0; r < 4; r++) {
        int pair = t + 256 * r;
        int el = pair >> 7, u = pair & 127;
        int p = p0 + el;
        float xj = g_x[s_send[el] * 128 + u];
        float4 w4 = *(const float4*)&s_w4[el][u * 4];
        float pre = w4.x * xj * s_sh0[el];
        float wm0 = s_wmm[el][u * 2 + 0] * pre;
        float wm1 = s_wmm[el][u * 2 + 1] * pre;
        float gate = wm0 * xj * s_mm0[el];
        size_t b = (size_t)p * 128 + u;
        g_gate[b] = gate;
        g_wm1x[b] = wm1 * xj;
        float gx = gate * xj;
        float4 A;
        A.x = w4.x * gx; A.y = w4.y * gx; A.z = w4.z * gx; A.w = w4.w * gx;
        reinterpret_cast<float4*>(g_A)[b] = A;
    }
}

// ---------------- launch 5: aggregation + per-l linear (R2-exact) ----------------
__global__ void __launch_bounds__(128) k_agg(const float* __restrict__ ea,
                                             const float* __restrict__ Wlin,
                                             const float* __restrict__ Wmlin)
{
    __shared__ float s_msg[4][128 * 16];
    __shared__ float s_mm[4][128 * 4];
    __shared__ float s_d[4];
    int u = threadIdx.x;
    int n0 = blockIdx.x * 4;

    for (int tn = 0; tn < 4; tn++) {
        int n = n0 + tn;
        float acc[16], am[4];
#pragma unroll
        for (int m = 0; m < 16; m++) acc[m] = 0.f;
#pragma unroll
        for (int j = 0; j < 4; j++) am[j] = 0.f;
        float dl = 0.f;
        int pb = g_off[n], pe = g_off[n + 1];
        for (int p = pb; p < pe; p++) {
            int e = g_perm[p];
            size_t b = (size_t)p * 128 + u;
            float4 A = reinterpret_cast<const float4*>(g_A)[b];
            float gate = g_gate[b];
            float wx = g_wm1x[b];
            const float* sh = ea + (size_t)e * 16;
            acc[0] += A.x * __ldg(sh + 0);
            acc[1] += A.y * __ldg(sh + 1);
            acc[2] += A.y * __ldg(sh + 2);
            acc[3] += A.y * __ldg(sh + 3);
#pragma unroll
            for (int m = 4; m < 9; m++) acc[m] += A.z * __ldg(sh + m);
#pragma unroll
            for (int m = 9; m < 16; m++) acc[m] += A.w * __ldg(sh + m);
            am[0] += gate;
            am[1] += wx * __ldg(&g_mmsh3[p * 3 + 0]);
            am[2] += wx * __ldg(&g_mmsh3[p * 3 + 1]);
            am[3] += wx * __ldg(&g_mmsh3[p * 3 + 2]);
            dl += __ldg(&g_dens[p]);
        }
#pragma unroll
        for (int m = 0; m < 16; m++) s_msg[tn][u * 16 + m] = acc[m];
#pragma unroll
        for (int j = 0; j < 4; j++) s_mm[tn][u * 4 + j] = am[j];
        if (u == 0) s_d[tn] = dl;
    }
    __syncthreads();

    int v = u;
    float lin[4][16];
    float lmm[4][4];
#pragma unroll
    for (int tn = 0; tn < 4; tn++) {
#pragma unroll
        for (int m = 0; m < 16; m++) lin[tn][m] = 0.f;
#pragma unroll
        for (int j = 0; j < 4; j++) lmm[tn][j] = 0.f;
    }
    for (int uu = 0; uu < 128; uu++) {
        float w0 = Wlin[(0 * 128 + uu) * 128 + v];
        float w1 = Wlin[(1 * 128 + uu) * 128 + v];
        float w2 = Wlin[(2 * 128 + uu) * 128 + v];
        float w3 = Wlin[(3 * 128 + uu) * 128 + v];
        float m0 = Wmlin[(0 * 128 + uu) * 128 + v];
        float m1 = Wmlin[(1 * 128 + uu) * 128 + v];
#pragma unroll
        for (int tn = 0; tn < 4; tn++) {
            const float4* mp = reinterpret_cast<const float4*>(&s_msg[tn][uu * 16]);
            float4 q0 = mp[0], q1 = mp[1], q2 = mp[2], q3 = mp[3];
            lin[tn][0]  += q0.x * w0;
            lin[tn][1]  += q0.y * w1;
            lin[tn][2]  += q0.z * w1;
            lin[tn][3]  += q0.w * w1;
            lin[tn][4]  += q1.x * w2;
            lin[tn][5]  += q1.y * w2;
            lin[tn][6]  += q1.z * w2;
            lin[tn][7]  += q1.w * w2;
            lin[tn][8]  += q2.x * w2;
            lin[tn][9]  += q2.y * w3;
            lin[tn][10] += q2.z * w3;
            lin[tn][11] += q2.w * w3;
            lin[tn][12] += q3.x * w3;
            lin[tn][13] += q3.y * w3;
            lin[tn][14] += q3.z * w3;
            lin[tn][15] += q3.w * w3;
            float4 mq = reinterpret_cast<const float4*>(&s_mm[tn][uu * 4])[0];
            lmm[tn][0] += mq.x * m0;
            lmm[tn][1] += mq.y * m1;
            lmm[tn][2] += mq.z * m1;
            lmm[tn][3] += mq.w * m1;
        }
    }
    const float sL = 0.08838834764831845f;
#pragma unroll
    for (int tn = 0; tn < 4; tn++) {
        float inv = sL / (s_d[tn] + 1.0f);
        size_t ob = ((size_t)(n0 + tn) * 128 + v) * 16;
#pragma unroll
        for (int m = 0; m < 16; m++) g_msglin[ob + m] = lin[tn][m] * inv;
        float im = sL * 0.05f;
        size_t ob2 = ((size_t)(n0 + tn) * 128 + v) * 4;
#pragma unroll
        for (int j = 0; j < 4; j++) g_mmlin[ob2 + j] = lmm[tn][j] * im;
    }
}

// ---------------- launch 6: mm skip path, NT=8, z-paired weights (R10 proven) ----------------
__global__ void __launch_bounds__(128) k_skipmm(const float* __restrict__ na,
                                                float* __restrict__ out)
{
    __shared__ float s_mml[8][512];
    int v = threadIdx.x;
    int n0 = blockIdx.x * 8;

    for (int tn = 0; tn < 8; tn++) {
        const float4* s2 = reinterpret_cast<const float4*>(&g_mmlin[(size_t)(n0 + tn) * 512]);
        reinterpret_cast<float4*>(s_mml[tn])[v] = s2[v];
    }
    float2 at2[8][5];
#pragma unroll
    for (int tn = 0; tn < 8; tn++)
#pragma unroll
        for (int k = 0; k < 5; k++)
            at2[tn][k] = f2(__ldg(&na[(n0 + tn) * 10 + 2 * k]),
                            __ldg(&na[(n0 + tn) * 10 + 2 * k + 1]));
    __syncthreads();

    float a2[8][4];
#pragma unroll
    for (int tn = 0; tn < 8; tn++)
#pragma unroll
        for (int j = 0; j < 4; j++) a2[tn][j] = 0.f;

    for (int uu = 0; uu < 128; uu++) {
        float t2[8][2];
#pragma unroll
        for (int l = 0; l < 2; l++) {
            const float2* W = &g_Wmp[((l * 128 + uu) * 5) * 128 + v];
            float2 w0 = __ldg(W), w1 = __ldg(W + 128), w2 = __ldg(W + 256);
            float2 w3 = __ldg(W + 384), w4 = __ldg(W + 512);
#pragma unroll
            for (int tn = 0; tn < 8; tn++) {
                float2 s = make_float2(0.f, 0.f);
                s = ffma2(at2[tn][0], w0, s);
                s = ffma2(at2[tn][1], w1, s);
                s = ffma2(at2[tn][2], w2, s);
                s = ffma2(at2[tn][3], w3, s);
                s = ffma2(at2[tn][4], w4, s);
                t2[tn][l] = s.x + s.y;
            }
        }
#pragma unroll
        for (int tn = 0; tn < 8; tn++) {
            float4 mq = reinterpret_cast<const float4*>(&s_mml[tn][uu * 4])[0];
            a2[tn][0] += mq.x * t2[tn][0];
            a2[tn][1] += mq.y * t2[tn][1];
            a2[tn][2] += mq.z * t2[tn][1];
            a2[tn][3] += mq.w * t2[tn][1];
        }
    }
    const float sc = 0.02795084971874737f;  // 1/sqrt(1280)
#pragma unroll
    for (int tn = 0; tn < 8; tn++) {
        size_t ob2 = (size_t)NN * 2048 + ((size_t)(n0 + tn) * 128 + v) * 16;
#pragma unroll
        for (int m = 0; m < 4; m++) out[ob2 + m] = a2[tn][m] * sc;
#pragma unroll
        for (int m = 4; m < 16; m++) out[ob2 + m] = 0.f;  // mm l=2,3 have no path
    }
}

// ---------------- launch 7: main skip TP, NT=8 as 2 independent groups of 128 ----------------
__global__ void __launch_bounds__(256) k_skip(const float* __restrict__ na,
                                              float* __restrict__ out)
{
    extern __shared__ float s_ml[];   // 8 * 2048 floats = 64KB dynamic
    int tid = threadIdx.x;
    int v = tid & 127;
    int g = tid >> 7;
    int n0 = blockIdx.x * 8;
    int nb = n0 + g * 4;

    // cooperative staging of all 8 nodes
    for (int tn = 0; tn < 8; tn++) {
        const float4* src = reinterpret_cast<const float4*>(&g_msglin[(size_t)(n0 + tn) * 2048]);
        float4* dst = reinterpret_cast<float4*>(&s_ml[tn * 2048]);
        for (int i = tid; i < 512; i += 256) dst[i] = src[i];
    }
    float2 at2[4][5];
#pragma unroll
    for (int tn = 0; tn < 4; tn++)
#pragma unroll
        for (int k = 0; k < 5; k++)
            at2[tn][k] = f2(__ldg(&na[(nb + tn) * 10 + 2 * k]),
                            __ldg(&na[(nb + tn) * 10 + 2 * k + 1]));
    __syncthreads();

    float a1[4][16];
#pragma unroll
    for (int tn = 0; tn < 4; tn++)
#pragma unroll
        for (int m = 0; m < 16; m++) a1[tn][m] = 0.f;

    for (int uu = 0; uu < 128; uu++) {
        float tt[4][4];
#pragma unroll
        for (int l = 0; l < 4; l++) {
            const float2* W = &g_Wp[((l * 128 + uu) * 5) * 128 + v];
            float2 w0 = __ldg(W), w1 = __ldg(W + 128), w2 = __ldg(W + 256);
            float2 w3 = __ldg(W + 384), w4 = __ldg(W + 512);
#pragma unroll
            for (int tn = 0; tn < 4; tn++) {
                float2 s = make_float2(0.f, 0.f);
                s = ffma2(at2[tn][0], w0, s);
                s = ffma2(at2[tn][1], w1, s);
                s = ffma2(at2[tn][2], w2, s);
                s = ffma2(at2[tn][3], w3, s);
                s = ffma2(at2[tn][4], w4, s);
                tt[tn][l] = s.x + s.y;
            }
        }
#pragma unroll
        for (int tn = 0; tn < 4; tn++) {
            const float4* mp = reinterpret_cast<const float4*>(&s_ml[(g * 4 + tn) * 2048 + uu * 16]);
            float4 q0 = mp[0], q1 = mp[1], q2 = mp[2], q3 = mp[3];
            a1[tn][0]  += q0.x * tt[tn][0];
            a1[tn][1]  += q0.y * tt[tn][1];
            a1[tn][2]  += q0.z * tt[tn][1];
            a1[tn][3]  += q0.w * tt[tn][1];
            a1[tn][4]  += q1.x * tt[tn][2];
            a1[tn][5]  += q1.y * tt[tn][2];
            a1[tn][6]  += q1.z * tt[tn][2];
            a1[tn][7]  += q1.w * tt[tn][2];
            a1[tn][8]  += q2.x * tt[tn][2];
            a1[tn][9]  += q2.y * tt[tn][3];
            a1[tn][10] += q2.z * tt[tn][3];
            a1[tn][11] += q2.w * tt[tn][3];
            a1[tn][12] += q3.x * tt[tn][3];
            a1[tn][13] += q3.y * tt[tn][3];
            a1[tn][14] += q3.z * tt[tn][3];
            a1[tn][15] += q3.w * tt[tn][3];
        }
    }
    const float sc = 0.02795084971874737f;  // 1/sqrt(1280)
#pragma unroll
    for (int tn = 0; tn < 4; tn++) {
        size_t ob = ((size_t)(nb + tn) * 128 + v) * 16;
#pragma unroll
        for (int m = 0; m < 16; m++) out[ob + m] = a1[tn][m] * sc;
    }
}

// ---------------- host ----------------
extern "C" void kernel_launch(void* const* d_in, const int* in_sizes, int n_in,
                              void* d_out, int out_size)
{
    const int* ei;
    int wi;
    if (in_sizes[6] == 2 * NE) { ei = (const int*)d_in[6]; wi = 7; }
    else                       { ei = (const int*)d_in[n_in - 1]; wi = 6; }

    const float* na   = (const float*)d_in[0];
    const float* nf   = (const float*)d_in[1];
    const float* ea   = (const float*)d_in[2];
    const float* ef   = (const float*)d_in[3];
    const float* mmi  = (const float*)d_in[4];
    const float* mma  = (const float*)d_in[5];
    const float* Wup  = (const float*)d_in[wi + 0];
    const float* W1   = (const float*)d_in[wi + 1];
    const float* W2   = (const float*)d_in[wi + 2];
    const float* W3   = (const float*)d_in[wi + 3];
    const float* W4   = (const float*)d_in[wi + 4];
    const float* M1   = (const float*)d_in[wi + 5];
    const float* M2   = (const float*)d_in[wi + 6];
    const float* M3   = (const float*)d_in[wi + 7];
    const float* M4   = (const float*)d_in[wi + 8];
    const float* Wd   = (const float*)d_in[wi + 9];
    const float* Wlin = (const float*)d_in[wi + 10];
    const float* Wmlin= (const float*)d_in[wi + 11];
    const float* Wsk  = (const float*)d_in[wi + 12];
    const float* Wmsk = (const float*)d_in[wi + 13];
    float* out = (float*)d_out;

    static bool attr_done = false;
    if (!attr_done) {
        cudaFuncSetAttribute(k_skip, cudaFuncAttributeMaxDynamicSharedMemorySize, 65536);
        attr_done = true;
    }

    k_hx<<<NN, 128>>>(nf, Wup, ei, Wsk, Wmsk);                    // 1: x + hist + weight pack
    k_scanmeff<<<1, 1024>>>(M1, M2, M3, M4);                      // 2
    k_scatter<<<(NE + 255) / 256, 256>>>(ei);                     // 3
    k_edge<<<NE / 8, 256>>>(W1, W2, W3, W4, ea, ef, mmi, mma, Wd, ei);  // 4 <- ncu slot
    k_agg<<<NN / 4, 128>>>(ea, Wlin, Wmlin);                      // 5
    k_skipmm<<<NN / 8, 128>>>(na, out);                           // 6
    k_skip<<<NN / 8, 256, 65536>>>(na, out);                      // 7
}

// round 13
// speedup vs baseline: 1.1586x; 1.1586x over previous
#include <cuda_runtime.h>
#include <math.h>
#include <stdint.h>

#define NN 5000
#define NE 100000
#define MULC 128

// ---------------- device scratch (static, no allocation) ----------------
__device__ float  g_x[NN * MULC];
__device__ float  g_Meff[16 * 256];
__device__ int    g_cnt[NN];
__device__ int    g_cur[NN];
__device__ int    g_off[NN + 1];
__device__ int    g_perm[NE];
__device__ float  g_A[(size_t)NE * MULC * 4];
__device__ float  g_gate[(size_t)NE * MULC];
__device__ float  g_wm1x[(size_t)NE * MULC];
__device__ float  g_mmsh3[NE * 3];
__device__ float  g_dens[NE];
__device__ float  g_msglin[NN * MULC * 16];
__device__ float  g_mmlin[NN * MULC * 4];
__device__ float2 g_Wp[4 * 128 * 5 * 128];   // Wsk z-paired: ((l*128+uu)*5+zp)*128+v
__device__ float2 g_Wmp[2 * 128 * 5 * 128];  // Wmsk l=0,1 z-paired

__device__ __forceinline__ float silu_f(float x) { return x / (1.0f + __expf(-x)); }
__device__ __forceinline__ float2 f2(float a, float b) { return make_float2(a, b); }
__device__ __forceinline__ float2 make2(float x) { return make_float2(x, x); }
__device__ __forceinline__ float2 ffma2(float2 a, float2 b, float2 c) {
    unsigned long long ra = *reinterpret_cast<unsigned long long*>(&a);
    unsigned long long rb = *reinterpret_cast<unsigned long long*>(&b);
    unsigned long long rc = *reinterpret_cast<unsigned long long*>(&c);
    unsigned long long rd;
    asm("fma.rn.f32x2 %0, %1, %2, %3;" : "=l"(rd) : "l"(ra), "l"(rb), "l"(rc));
    return *reinterpret_cast<float2*>(&rd);
}

// ---------------- launch 1: x = nf@Wup/sqrt(128) + receiver histogram + weight z-pair pack ----
__global__ void __launch_bounds__(128) k_hx(const float* __restrict__ nf,
                                            const float* __restrict__ Wup,
                                            const int* __restrict__ ei,
                                            const float* __restrict__ Wsk,
                                            const float* __restrict__ Wmsk) {
    __shared__ float s[128];
    int n = blockIdx.x, t = threadIdx.x;
    s[t] = nf[n * 128 + t];
    __syncthreads();
    float acc = 0.f;
#pragma unroll 8
    for (int u = 0; u < 128; u++) acc += s[u] * Wup[u * 128 + t];
    g_x[n * 128 + t] = acc * 0.08838834764831845f;
    int gid = n * 128 + t;
    if (gid < NE) atomicAdd(&g_cnt[ei[NE + gid]], 1);
    const int T1 = 4 * 128 * 5 * 128;
    const int T2 = 2 * 128 * 5 * 128;
    if (gid < T1) {
        int v = gid & 127;
        int zp = (gid >> 7) % 5;
        int lu = gid / (5 * 128);
        const float* b = Wsk + ((size_t)lu * 10 + 2 * zp) * 128 + v;
        g_Wp[gid] = f2(b[0], b[128]);
    } else if (gid < T1 + T2) {
        int j = gid - T1;
        int v = j & 127;
        int zp = (j >> 7) % 5;
        int lu = j / (5 * 128);
        const float* b = Wmsk + ((size_t)lu * 10 + 2 * zp) * 128 + v;
        g_Wmp[j] = f2(b[0], b[128]);
    }
}

// ---------------- launch 2: Meff + CSR scan + self-restore zeroing (1 block) ----------------
__global__ void __launch_bounds__(1024) k_scanmeff(
    const float* __restrict__ M1, const float* __restrict__ M2,
    const float* __restrict__ M3, const float* __restrict__ M4) {
    __shared__ float T1[16 * 64];
    __shared__ float T2[16 * 64];
    __shared__ int   s[1024];
    int t = threadIdx.x;
    for (int idx = t; idx < 16 * 64; idx += 1024) {
        int a = idx >> 6, k = idx & 63;
        float acc = 0.f;
        for (int b = 0; b < 64; b++) acc += M1[a * 64 + b] * M2[b * 64 + k];
        T1[idx] = acc;
    }
    __syncthreads();
    for (int idx = t; idx < 16 * 64; idx += 1024) {
        int a = idx >> 6, k = idx & 63;
        float acc = 0.f;
        for (int b = 0; b < 64; b++) acc += T1[a * 64 + b] * M3[b * 64 + k];
        T2[idx] = acc;
    }
    __syncthreads();
    for (int idx = t; idx < 16 * 256; idx += 1024) {
        int a = idx >> 8, c = idx & 255;
        float acc = 0.f;
        for (int b = 0; b < 64; b++) acc += T2[a * 64 + b] * M4[b * 256 + c];
        g_Meff[idx] = acc * 4.8828125e-4f;
    }
    int carry = 0;
    for (int base = 0; base < NN; base += 1024) {
        int i = base + t;
        int c = (i < NN) ? g_cnt[i] : 0;
        s[t] = c;
        __syncthreads();
        for (int d = 1; d < 1024; d <<= 1) {
            int v = (t >= d) ? s[t - d] : 0;
            __syncthreads();
            s[t] += v;
            __syncthreads();
        }
        if (i < NN) g_off[i] = carry + s[t] - c;
        carry += s[1023];
        __syncthreads();
    }
    if (t == 0) g_off[NN] = NE;
    __syncthreads();
    for (int i = t; i < NN; i += 1024) { g_cnt[i] = 0; g_cur[i] = 0; }
}

// ---------------- launch 3: scatter edges into CSR order ----------------
__global__ void __launch_bounds__(256) k_scatter(const int* __restrict__ ei) {
    int e = blockIdx.x * blockDim.x + threadIdx.x;
    if (e < NE) {
        int r = ei[NE + e];
        int k = atomicAdd(&g_cur[r], 1);
        g_perm[g_off[r] + k] = e;
    }
}

// ---------------- launch 4: edge kernel (R11 version — measured 350us) ----------------
__global__ void __launch_bounds__(256) k_edge(
    const float* __restrict__ W1, const float* __restrict__ W2,
    const float* __restrict__ W3, const float* __restrict__ W4,
    const float* __restrict__ ea, const float* __restrict__ ef,
    const float* __restrict__ mmi, const float* __restrict__ mma,
    const float* __restrict__ Wd, const int* __restrict__ ei)
{
    __shared__ float s_efT[16][8];     // [j][el]
    __shared__ float s_h1T[64][12];    // [j][el], pad 12 (16B-aligned rows)
    __shared__ float s_h2T[64][12];
    __shared__ float s_h3T[64][12];
    __shared__ float s_w4[8][512];
    __shared__ float s_wmm[8][256];
    __shared__ int   s_e[8], s_send[8];
    __shared__ float s_sh0[8], s_mm0[8];

    int t = threadIdx.x;
    int p0 = blockIdx.x * 8;

    if (t < 8) {
        int e = g_perm[p0 + t];
        s_e[t] = e;
        s_send[t] = ei[e];
    }
    __syncthreads();
    if (t < 128) {
        int el = t >> 4, j = t & 15;
        int e = s_e[el], sd = s_send[el];
        s_efT[j][el] = (j < 8) ? ef[e * 8 + j] : mmi[sd * 8 + (j - 8)];
    }
    __syncthreads();

    int i = t & 63;    // output neuron
    int ep = t >> 6;   // edge-pair 0..3
    {
        float2 a = make_float2(0.f, 0.f);
#pragma unroll
        for (int j = 0; j < 16; j++)
            a = ffma2(*(const float2*)&s_efT[j][2 * ep], make2(W1[j * 64 + i]), a);
        *(float2*)&s_h1T[i][2 * ep] = f2(silu_f(a.x * 0.25f), silu_f(a.y * 0.25f));
    }
    __syncthreads();
    {
        float2 a = make_float2(0.f, 0.f);
#pragma unroll 8
        for (int j = 0; j < 64; j++)
            a = ffma2(*(const float2*)&s_h1T[j][2 * ep], make2(W2[j * 64 + i]), a);
        *(float2*)&s_h2T[i][2 * ep] = f2(silu_f(a.x * 0.125f), silu_f(a.y * 0.125f));
    }
    __syncthreads();
    {
        float2 a = make_float2(0.f, 0.f);
#pragma unroll 8
        for (int j = 0; j < 64; j++)
            a = ffma2(*(const float2*)&s_h2T[j][2 * ep], make2(W3[j * 64 + i]), a);
        *(float2*)&s_h3T[i][2 * ep] = f2(silu_f(a.x * 0.125f), silu_f(a.y * 0.125f));
    }
    __syncthreads();
    {
        float2 a0[4], a1[4];
#pragma unroll
        for (int p = 0; p < 4; p++) { a0[p] = make_float2(0.f, 0.f); a1[p] = make_float2(0.f, 0.f); }
#pragma unroll 4
        for (int j = 0; j < 64; j++) {
            float2 w = *(const float2*)&W4[j * 512 + 2 * t];
            float4 h0 = *(const float4*)&s_h3T[j][0];
            float4 h1 = *(const float4*)&s_h3T[j][4];
            float2 hp0 = f2(h0.x, h0.y), hp1 = f2(h0.z, h0.w);
            float2 hp2 = f2(h1.x, h1.y), hp3 = f2(h1.z, h1.w);
            float2 w0 = make2(w.x), w1 = make2(w.y);
            a0[0] = ffma2(hp0, w0, a0[0]); a1[0] = ffma2(hp0, w1, a1[0]);
            a0[1] = ffma2(hp1, w0, a0[1]); a1[1] = ffma2(hp1, w1, a1[1]);
            a0[2] = ffma2(hp2, w0, a0[2]); a1[2] = ffma2(hp2, w1, a1[2]);
            a0[3] = ffma2(hp3, w0, a0[3]); a1[3] = ffma2(hp3, w1, a1[3]);
        }
#pragma unroll
        for (int p = 0; p < 4; p++) {
            s_w4[2 * p][2 * t]         = a0[p].x * 0.125f;
            s_w4[2 * p + 1][2 * t]     = a0[p].y * 0.125f;
            s_w4[2 * p][2 * t + 1]     = a1[p].x * 0.125f;
            s_w4[2 * p + 1][2 * t + 1] = a1[p].y * 0.125f;
        }
    }
    {
        float2 ac[4];
#pragma unroll
        for (int p = 0; p < 4; p++) ac[p] = make_float2(0.f, 0.f);
#pragma unroll
        for (int j = 0; j < 16; j++) {
            float2 m = make2(g_Meff[j * 256 + t]);
            float4 e0 = *(const float4*)&s_efT[j][0];
            float4 e1 = *(const float4*)&s_efT[j][4];
            ac[0] = ffma2(f2(e0.x, e0.y), m, ac[0]);
            ac[1] = ffma2(f2(e0.z, e0.w), m, ac[1]);
            ac[2] = ffma2(f2(e1.x, e1.y), m, ac[2]);
            ac[3] = ffma2(f2(e1.z, e1.w), m, ac[3]);
        }
#pragma unroll
        for (int p = 0; p < 4; p++) {
            s_wmm[2 * p][t]     = ac[p].x;
            s_wmm[2 * p + 1][t] = ac[p].y;
        }
    }
    if (t < 8) {
        int el = t;
        int e = s_e[el], sd = s_send[el];
        s_sh0[el] = ea[(size_t)e * 16];
        float q = 0.f;
#pragma unroll
        for (int j = 0; j < 8; j++) q += ef[e * 8 + j] * Wd[j];
        q *= 0.35355339059327373f;
        g_dens[p0 + el] = tanhf(q * q);
        s_mm0[el] = mma[sd * 4];
        g_mmsh3[(p0 + el) * 3 + 0] = mma[sd * 4 + 1];
        g_mmsh3[(p0 + el) * 3 + 1] = mma[sd * 4 + 2];
        g_mmsh3[(p0 + el) * 3 + 2] = mma[sd * 4 + 3];
    }
    __syncthreads();
#pragma unroll
    for (int r = 0; r < 4; r++) {
        int pair = t + 256 * r;
        int el = pair >> 7, u = pair & 127;
        int p = p0 + el;
        float xj = g_x[s_send[el] * 128 + u];
        float4 w4 = *(const float4*)&s_w4[el][u * 4];
        float pre = w4.x * xj * s_sh0[el];
        float wm0 = s_wmm[el][u * 2 + 0] * pre;
        float wm1 = s_wmm[el][u * 2 + 1] * pre;
        float gate = wm0 * xj * s_mm0[el];
        size_t b = (size_t)p * 128 + u;
        g_gate[b] = gate;
        g_wm1x[b] = wm1 * xj;
        float gx = gate * xj;
        float4 A;
        A.x = w4.x * gx; A.y = w4.y * gx; A.z = w4.z * gx; A.w = w4.w * gx;
        reinterpret_cast<float4*>(g_A)[b] = A;
    }
}

// ---------------- launch 5: aggregation + per-l linear (R2-exact) ----------------
__global__ void __launch_bounds__(128) k_agg(const float* __restrict__ ea,
                                             const float* __restrict__ Wlin,
                                             const float* __restrict__ Wmlin)
{
    __shared__ float s_msg[4][128 * 16];
    __shared__ float s_mm[4][128 * 4];
    __shared__ float s_d[4];
    int u = threadIdx.x;
    int n0 = blockIdx.x * 4;

    for (int tn = 0; tn < 4; tn++) {
        int n = n0 + tn;
        float acc[16], am[4];
#pragma unroll
        for (int m = 0; m < 16; m++) acc[m] = 0.f;
#pragma unroll
        for (int j = 0; j < 4; j++) am[j] = 0.f;
        float dl = 0.f;
        int pb = g_off[n], pe = g_off[n + 1];
        for (int p = pb; p < pe; p++) {
            int e = g_perm[p];
            size_t b = (size_t)p * 128 + u;
            float4 A = reinterpret_cast<const float4*>(g_A)[b];
            float gate = g_gate[b];
            float wx = g_wm1x[b];
            const float* sh = ea + (size_t)e * 16;
            acc[0] += A.x * __ldg(sh + 0);
            acc[1] += A.y * __ldg(sh + 1);
            acc[2] += A.y * __ldg(sh + 2);
            acc[3] += A.y * __ldg(sh + 3);
#pragma unroll
            for (int m = 4; m < 9; m++) acc[m] += A.z * __ldg(sh + m);
#pragma unroll
            for (int m = 9; m < 16; m++) acc[m] += A.w * __ldg(sh + m);
            am[0] += gate;
            am[1] += wx * __ldg(&g_mmsh3[p * 3 + 0]);
            am[2] += wx * __ldg(&g_mmsh3[p * 3 + 1]);
            am[3] += wx * __ldg(&g_mmsh3[p * 3 + 2]);
            dl += __ldg(&g_dens[p]);
        }
#pragma unroll
        for (int m = 0; m < 16; m++) s_msg[tn][u * 16 + m] = acc[m];
#pragma unroll
        for (int j = 0; j < 4; j++) s_mm[tn][u * 4 + j] = am[j];
        if (u == 0) s_d[tn] = dl;
    }
    __syncthreads();

    int v = u;
    float lin[4][16];
    float lmm[4][4];
#pragma unroll
    for (int tn = 0; tn < 4; tn++) {
#pragma unroll
        for (int m = 0; m < 16; m++) lin[tn][m] = 0.f;
#pragma unroll
        for (int j = 0; j < 4; j++) lmm[tn][j] = 0.f;
    }
    for (int uu = 0; uu < 128; uu++) {
        float w0 = Wlin[(0 * 128 + uu) * 128 + v];
        float w1 = Wlin[(1 * 128 + uu) * 128 + v];
        float w2 = Wlin[(2 * 128 + uu) * 128 + v];
        float w3 = Wlin[(3 * 128 + uu) * 128 + v];
        float m0 = Wmlin[(0 * 128 + uu) * 128 + v];
        float m1 = Wmlin[(1 * 128 + uu) * 128 + v];
#pragma unroll
        for (int tn = 0; tn < 4; tn++) {
            const float4* mp = reinterpret_cast<const float4*>(&s_msg[tn][uu * 16]);
            float4 q0 = mp[0], q1 = mp[1], q2 = mp[2], q3 = mp[3];
            lin[tn][0]  += q0.x * w0;
            lin[tn][1]  += q0.y * w1;
            lin[tn][2]  += q0.z * w1;
            lin[tn][3]  += q0.w * w1;
            lin[tn][4]  += q1.x * w2;
            lin[tn][5]  += q1.y * w2;
            lin[tn][6]  += q1.z * w2;
            lin[tn][7]  += q1.w * w2;
            lin[tn][8]  += q2.x * w2;
            lin[tn][9]  += q2.y * w3;
            lin[tn][10] += q2.z * w3;
            lin[tn][11] += q2.w * w3;
            lin[tn][12] += q3.x * w3;
            lin[tn][13] += q3.y * w3;
            lin[tn][14] += q3.z * w3;
            lin[tn][15] += q3.w * w3;
            float4 mq = reinterpret_cast<const float4*>(&s_mm[tn][uu * 4])[0];
            lmm[tn][0] += mq.x * m0;
            lmm[tn][1] += mq.y * m1;
            lmm[tn][2] += mq.z * m1;
            lmm[tn][3] += mq.w * m1;
        }
    }
    const float sL = 0.08838834764831845f;
#pragma unroll
    for (int tn = 0; tn < 4; tn++) {
        float inv = sL / (s_d[tn] + 1.0f);
        size_t ob = ((size_t)(n0 + tn) * 128 + v) * 16;
#pragma unroll
        for (int m = 0; m < 16; m++) g_msglin[ob + m] = lin[tn][m] * inv;
        float im = sL * 0.05f;
        size_t ob2 = ((size_t)(n0 + tn) * 128 + v) * 4;
#pragma unroll
        for (int j = 0; j < 4; j++) g_mmlin[ob2 + j] = lmm[tn][j] * im;
    }
}

// ---------------- launch 6: mm skip path, NT=8, z-paired weights (R10 proven) ----------------
__global__ void __launch_bounds__(128) k_skipmm(const float* __restrict__ na,
                                                float* __restrict__ out)
{
    __shared__ float s_mml[8][512];
    int v = threadIdx.x;
    int n0 = blockIdx.x * 8;

    for (int tn = 0; tn < 8; tn++) {
        const float4* s2 = reinterpret_cast<const float4*>(&g_mmlin[(size_t)(n0 + tn) * 512]);
        reinterpret_cast<float4*>(s_mml[tn])[v] = s2[v];
    }
    float2 at2[8][5];
#pragma unroll
    for (int tn = 0; tn < 8; tn++)
#pragma unroll
        for (int k = 0; k < 5; k++)
            at2[tn][k] = f2(__ldg(&na[(n0 + tn) * 10 + 2 * k]),
                            __ldg(&na[(n0 + tn) * 10 + 2 * k + 1]));
    __syncthreads();

    float a2[8][4];
#pragma unroll
    for (int tn = 0; tn < 8; tn++)
#pragma unroll
        for (int j = 0; j < 4; j++) a2[tn][j] = 0.f;

    for (int uu = 0; uu < 128; uu++) {
        float t2[8][2];
#pragma unroll
        for (int l = 0; l < 2; l++) {
            const float2* W = &g_Wmp[((l * 128 + uu) * 5) * 128 + v];
            float2 w0 = __ldg(W), w1 = __ldg(W + 128), w2 = __ldg(W + 256);
            float2 w3 = __ldg(W + 384), w4 = __ldg(W + 512);
#pragma unroll
            for (int tn = 0; tn < 8; tn++) {
                float2 s = make_float2(0.f, 0.f);
                s = ffma2(at2[tn][0], w0, s);
                s = ffma2(at2[tn][1], w1, s);
                s = ffma2(at2[tn][2], w2, s);
                s = ffma2(at2[tn][3], w3, s);
                s = ffma2(at2[tn][4], w4, s);
                t2[tn][l] = s.x + s.y;
            }
        }
#pragma unroll
        for (int tn = 0; tn < 8; tn++) {
            float4 mq = reinterpret_cast<const float4*>(&s_mml[tn][uu * 4])[0];
            a2[tn][0] += mq.x * t2[tn][0];
            a2[tn][1] += mq.y * t2[tn][1];
            a2[tn][2] += mq.z * t2[tn][1];
            a2[tn][3] += mq.w * t2[tn][1];
        }
    }
    const float sc = 0.02795084971874737f;  // 1/sqrt(1280)
#pragma unroll
    for (int tn = 0; tn < 8; tn++) {
        size_t ob2 = (size_t)NN * 2048 + ((size_t)(n0 + tn) * 128 + v) * 16;
#pragma unroll
        for (int m = 0; m < 4; m++) out[ob2 + m] = a2[tn][m] * sc;
#pragma unroll
        for (int m = 4; m < 16; m++) out[ob2 + m] = 0.f;  // mm l=2,3 have no path
    }
}

// ---------------- launch 7: main skip TP, NT=4, z-paired ffma2 (R10 proven) ----------------
__global__ void __launch_bounds__(128) k_skip(const float* __restrict__ na,
                                              float* __restrict__ out)
{
    __shared__ float s_ml[4][2048];
    int v = threadIdx.x;
    int n0 = blockIdx.x * 4;

    for (int tn = 0; tn < 4; tn++) {
        const float4* src = reinterpret_cast<const float4*>(&g_msglin[(size_t)(n0 + tn) * 2048]);
        float4* dst = reinterpret_cast<float4*>(s_ml[tn]);
        for (int i = v; i < 512; i += 128) dst[i] = src[i];
    }
    float2 at2[4][5];
#pragma unroll
    for (int tn = 0; tn < 4; tn++)
#pragma unroll
        for (int k = 0; k < 5; k++)
            at2[tn][k] = f2(__ldg(&na[(n0 + tn) * 10 + 2 * k]),
                            __ldg(&na[(n0 + tn) * 10 + 2 * k + 1]));
    __syncthreads();

    float a1[4][16];
#pragma unroll
    for (int tn = 0; tn < 4; tn++)
#pragma unroll
        for (int m = 0; m < 16; m++) a1[tn][m] = 0.f;

    for (int uu = 0; uu < 128; uu++) {
        float tt[4][4];
#pragma unroll
        for (int l = 0; l < 4; l++) {
            const float2* W = &g_Wp[((l * 128 + uu) * 5) * 128 + v];
            float2 w0 = __ldg(W), w1 = __ldg(W + 128), w2 = __ldg(W + 256);
            float2 w3 = __ldg(W + 384), w4 = __ldg(W + 512);
#pragma unroll
            for (int tn = 0; tn < 4; tn++) {
                float2 s = make_float2(0.f, 0.f);
                s = ffma2(at2[tn][0], w0, s);
                s = ffma2(at2[tn][1], w1, s);
                s = ffma2(at2[tn][2], w2, s);
                s = ffma2(at2[tn][3], w3, s);
                s = ffma2(at2[tn][4], w4, s);
                tt[tn][l] = s.x + s.y;
            }
        }
#pragma unroll
        for (int tn = 0; tn < 4; tn++) {
            const float4* mp = reinterpret_cast<const float4*>(&s_ml[tn][uu * 16]);
            float4 q0 = mp[0], q1 = mp[1], q2 = mp[2], q3 = mp[3];
            a1[tn][0]  += q0.x * tt[tn][0];
            a1[tn][1]  += q0.y * tt[tn][1];
            a1[tn][2]  += q0.z * tt[tn][1];
            a1[tn][3]  += q0.w * tt[tn][1];
            a1[tn][4]  += q1.x * tt[tn][2];
            a1[tn][5]  += q1.y * tt[tn][2];
            a1[tn][6]  += q1.z * tt[tn][2];
            a1[tn][7]  += q1.w * tt[tn][2];
            a1[tn][8]  += q2.x * tt[tn][2];
            a1[tn][9]  += q2.y * tt[tn][3];
            a1[tn][10] += q2.z * tt[tn][3];
            a1[tn][11] += q2.w * tt[tn][3];
            a1[tn][12] += q3.x * tt[tn][3];
            a1[tn][13] += q3.y * tt[tn][3];
            a1[tn][14] += q3.z * tt[tn][3];
            a1[tn][15] += q3.w * tt[tn][3];
        }
    }
    const float sc = 0.02795084971874737f;  // 1/sqrt(1280)
#pragma unroll
    for (int tn = 0; tn < 4; tn++) {
        size_t ob = ((size_t)(n0 + tn) * 128 + v) * 16;
#pragma unroll
        for (int m = 0; m < 16; m++) out[ob + m] = a1[tn][m] * sc;
    }
}

// ---------------- host ----------------
extern "C" void kernel_launch(void* const* d_in, const int* in_sizes, int n_in,
                              void* d_out, int out_size)
{
    const int* ei;
    int wi;
    if (in_sizes[6] == 2 * NE) { ei = (const int*)d_in[6]; wi = 7; }
    else                       { ei = (const int*)d_in[n_in - 1]; wi = 6; }

    const float* na   = (const float*)d_in[0];
    const float* nf   = (const float*)d_in[1];
    const float* ea   = (const float*)d_in[2];
    const float* ef   = (const float*)d_in[3];
    const float* mmi  = (const float*)d_in[4];
    const float* mma  = (const float*)d_in[5];
    const float* Wup  = (const float*)d_in[wi + 0];
    const float* W1   = (const float*)d_in[wi + 1];
    const float* W2   = (const float*)d_in[wi + 2];
    const float* W3   = (const float*)d_in[wi + 3];
    const float* W4   = (const float*)d_in[wi + 4];
    const float* M1   = (const float*)d_in[wi + 5];
    const float* M2   = (const float*)d_in[wi + 6];
    const float* M3   = (const float*)d_in[wi + 7];
    const float* M4   = (const float*)d_in[wi + 8];
    const float* Wd   = (const float*)d_in[wi + 9];
    const float* Wlin = (const float*)d_in[wi + 10];
    const float* Wmlin= (const float*)d_in[wi + 11];
    const float* Wsk  = (const float*)d_in[wi + 12];
    const float* Wmsk = (const float*)d_in[wi + 13];
    float* out = (float*)d_out;

    k_hx<<<NN, 128>>>(nf, Wup, ei, Wsk, Wmsk);                    // 1: x + hist + weight pack
    k_scanmeff<<<1, 1024>>>(M1, M2, M3, M4);                      // 2
    k_scatter<<<(NE + 255) / 256, 256>>>(ei);                     // 3
    k_edge<<<NE / 8, 256>>>(W1, W2, W3, W4, ea, ef, mmi, mma, Wd, ei);  // 4 <- ncu slot
    k_agg<<<NN / 4, 128>>>(ea, Wlin, Wmlin);                      // 5
    k_skipmm<<<NN / 8, 128>>>(na, out);                           // 6
    k_skip<<<NN / 4, 128>>>(na, out);                             // 7
}

// round 14
// speedup vs baseline: 1.1725x; 1.0120x over previous
#include <cuda_runtime.h>
#include <math.h>
#include <stdint.h>

#define NN 5000
#define NE 100000
#define MULC 128

// ---------------- device scratch (static, no allocation) ----------------
__device__ float  g_x[NN * MULC];
__device__ float  g_Meff[16 * 256];
__device__ int    g_cnt[NN];
__device__ int    g_cur[NN];
__device__ int    g_off[NN + 1];
__device__ int    g_perm[NE];
__device__ float  g_A[(size_t)NE * MULC * 4];
__device__ float  g_gate[(size_t)NE * MULC];
__device__ float  g_wm1x[(size_t)NE * MULC];
__device__ float  g_mmsh3[NE * 3];
__device__ float  g_dens[NE];
__device__ float  g_msglin[NN * MULC * 16];
__device__ float  g_mmlin[NN * MULC * 4];
__device__ float2 g_Wp[4 * 128 * 5 * 128];   // Wsk z-paired: ((l*128+uu)*5+zp)*128+v
__device__ float2 g_Wmp[2 * 128 * 5 * 128];  // Wmsk l=0,1 z-paired

__device__ __forceinline__ float silu_f(float x) { return x / (1.0f + __expf(-x)); }
__device__ __forceinline__ float2 f2(float a, float b) { return make_float2(a, b); }
__device__ __forceinline__ float2 make2(float x) { return make_float2(x, x); }
__device__ __forceinline__ float2 ffma2(float2 a, float2 b, float2 c) {
    unsigned long long ra = *reinterpret_cast<unsigned long long*>(&a);
    unsigned long long rb = *reinterpret_cast<unsigned long long*>(&b);
    unsigned long long rc = *reinterpret_cast<unsigned long long*>(&c);
    unsigned long long rd;
    asm("fma.rn.f32x2 %0, %1, %2, %3;" : "=l"(rd) : "l"(ra), "l"(rb), "l"(rc));
    return *reinterpret_cast<float2*>(&rd);
}

// ---------------- launch 1: x = nf@Wup/sqrt(128) + receiver histogram + weight z-pair pack ----
__global__ void __launch_bounds__(128) k_hx(const float* __restrict__ nf,
                                            const float* __restrict__ Wup,
                                            const int* __restrict__ ei,
                                            const float* __restrict__ Wsk,
                                            const float* __restrict__ Wmsk) {
    __shared__ float s[128];
    int n = blockIdx.x, t = threadIdx.x;
    s[t] = nf[n * 128 + t];
    __syncthreads();
    float acc = 0.f;
#pragma unroll 8
    for (int u = 0; u < 128; u++) acc += s[u] * Wup[u * 128 + t];
    g_x[n * 128 + t] = acc * 0.08838834764831845f;
    int gid = n * 128 + t;
    if (gid < NE) atomicAdd(&g_cnt[ei[NE + gid]], 1);
    const int T1 = 4 * 128 * 5 * 128;
    const int T2 = 2 * 128 * 5 * 128;
    if (gid < T1) {
        int v = gid & 127;
        int zp = (gid >> 7) % 5;
        int lu = gid / (5 * 128);
        const float* b = Wsk + ((size_t)lu * 10 + 2 * zp) * 128 + v;
        g_Wp[gid] = f2(b[0], b[128]);
    } else if (gid < T1 + T2) {
        int j = gid - T1;
        int v = j & 127;
        int zp = (j >> 7) % 5;
        int lu = j / (5 * 128);
        const float* b = Wmsk + ((size_t)lu * 10 + 2 * zp) * 128 + v;
        g_Wmp[j] = f2(b[0], b[128]);
    }
}

// ---------------- launch 2: Meff + CSR scan + self-restore zeroing (1 block) ----------------
__global__ void __launch_bounds__(1024) k_scanmeff(
    const float* __restrict__ M1, const float* __restrict__ M2,
    const float* __restrict__ M3, const float* __restrict__ M4) {
    __shared__ float T1[16 * 64];
    __shared__ float T2[16 * 64];
    __shared__ int   s[1024];
    int t = threadIdx.x;
    for (int idx = t; idx < 16 * 64; idx += 1024) {
        int a = idx >> 6, k = idx & 63;
        float acc = 0.f;
        for (int b = 0; b < 64; b++) acc += M1[a * 64 + b] * M2[b * 64 + k];
        T1[idx] = acc;
    }
    __syncthreads();
    for (int idx = t; idx < 16 * 64; idx += 1024) {
        int a = idx >> 6, k = idx & 63;
        float acc = 0.f;
        for (int b = 0; b < 64; b++) acc += T1[a * 64 + b] * M3[b * 64 + k];
        T2[idx] = acc;
    }
    __syncthreads();
    for (int idx = t; idx < 16 * 256; idx += 1024) {
        int a = idx >> 8, c = idx & 255;
        float acc = 0.f;
        for (int b = 0; b < 64; b++) acc += T2[a * 64 + b] * M4[b * 256 + c];
        g_Meff[idx] = acc * 4.8828125e-4f;
    }
    int carry = 0;
    for (int base = 0; base < NN; base += 1024) {
        int i = base + t;
        int c = (i < NN) ? g_cnt[i] : 0;
        s[t] = c;
        __syncthreads();
        for (int d = 1; d < 1024; d <<= 1) {
            int v = (t >= d) ? s[t - d] : 0;
            __syncthreads();
            s[t] += v;
            __syncthreads();
        }
        if (i < NN) g_off[i] = carry + s[t] - c;
        carry += s[1023];
        __syncthreads();
    }
    if (t == 0) g_off[NN] = NE;
    __syncthreads();
    for (int i = t; i < NN; i += 1024) { g_cnt[i] = 0; g_cur[i] = 0; }
}

// ---------------- launch 3: scatter edges into CSR order ----------------
__global__ void __launch_bounds__(256) k_scatter(const int* __restrict__ ei) {
    int e = blockIdx.x * blockDim.x + threadIdx.x;
    if (e < NE) {
        int r = ei[NE + e];
        int k = atomicAdd(&g_cur[r], 1);
        g_perm[g_off[r] + k] = e;
    }
}

// ---------------- launch 4: edge kernel (R11/R12 version — measured 329us) ----------------
__global__ void __launch_bounds__(256) k_edge(
    const float* __restrict__ W1, const float* __restrict__ W2,
    const float* __restrict__ W3, const float* __restrict__ W4,
    const float* __restrict__ ea, const float* __restrict__ ef,
    const float* __restrict__ mmi, const float* __restrict__ mma,
    const float* __restrict__ Wd, const int* __restrict__ ei)
{
    __shared__ float s_efT[16][8];     // [j][el]
    __shared__ float s_h1T[64][12];    // [j][el], pad 12 (16B-aligned rows)
    __shared__ float s_h2T[64][12];
    __shared__ float s_h3T[64][12];
    __shared__ float s_w4[8][512];
    __shared__ float s_wmm[8][256];
    __shared__ int   s_e[8], s_send[8];
    __shared__ float s_sh0[8], s_mm0[8];

    int t = threadIdx.x;
    int p0 = blockIdx.x * 8;

    if (t < 8) {
        int e = g_perm[p0 + t];
        s_e[t] = e;
        s_send[t] = ei[e];
    }
    __syncthreads();
    if (t < 128) {
        int el = t >> 4, j = t & 15;
        int e = s_e[el], sd = s_send[el];
        s_efT[j][el] = (j < 8) ? ef[e * 8 + j] : mmi[sd * 8 + (j - 8)];
    }
    __syncthreads();

    int i = t & 63;    // output neuron
    int ep = t >> 6;   // edge-pair 0..3
    {
        float2 a = make_float2(0.f, 0.f);
#pragma unroll
        for (int j = 0; j < 16; j++)
            a = ffma2(*(const float2*)&s_efT[j][2 * ep], make2(W1[j * 64 + i]), a);
        *(float2*)&s_h1T[i][2 * ep] = f2(silu_f(a.x * 0.25f), silu_f(a.y * 0.25f));
    }
    __syncthreads();
    {
        float2 a = make_float2(0.f, 0.f);
#pragma unroll 8
        for (int j = 0; j < 64; j++)
            a = ffma2(*(const float2*)&s_h1T[j][2 * ep], make2(W2[j * 64 + i]), a);
        *(float2*)&s_h2T[i][2 * ep] = f2(silu_f(a.x * 0.125f), silu_f(a.y * 0.125f));
    }
    __syncthreads();
    {
        float2 a = make_float2(0.f, 0.f);
#pragma unroll 8
        for (int j = 0; j < 64; j++)
            a = ffma2(*(const float2*)&s_h2T[j][2 * ep], make2(W3[j * 64 + i]), a);
        *(float2*)&s_h3T[i][2 * ep] = f2(silu_f(a.x * 0.125f), silu_f(a.y * 0.125f));
    }
    __syncthreads();
    {
        float2 a0[4], a1[4];
#pragma unroll
        for (int p = 0; p < 4; p++) { a0[p] = make_float2(0.f, 0.f); a1[p] = make_float2(0.f, 0.f); }
#pragma unroll 4
        for (int j = 0; j < 64; j++) {
            float2 w = *(const float2*)&W4[j * 512 + 2 * t];
            float4 h0 = *(const float4*)&s_h3T[j][0];
            float4 h1 = *(const float4*)&s_h3T[j][4];
            float2 hp0 = f2(h0.x, h0.y), hp1 = f2(h0.z, h0.w);
            float2 hp2 = f2(h1.x, h1.y), hp3 = f2(h1.z, h1.w);
            float2 w0 = make2(w.x), w1 = make2(w.y);
            a0[0] = ffma2(hp0, w0, a0[0]); a1[0] = ffma2(hp0, w1, a1[0]);
            a0[1] = ffma2(hp1, w0, a0[1]); a1[1] = ffma2(hp1, w1, a1[1]);
            a0[2] = ffma2(hp2, w0, a0[2]); a1[2] = ffma2(hp2, w1, a1[2]);
            a0[3] = ffma2(hp3, w0, a0[3]); a1[3] = ffma2(hp3, w1, a1[3]);
        }
#pragma unroll
        for (int p = 0; p < 4; p++) {
            s_w4[2 * p][2 * t]         = a0[p].x * 0.125f;
            s_w4[2 * p + 1][2 * t]     = a0[p].y * 0.125f;
            s_w4[2 * p][2 * t + 1]     = a1[p].x * 0.125f;
            s_w4[2 * p + 1][2 * t + 1] = a1[p].y * 0.125f;
        }
    }
    {
        float2 ac[4];
#pragma unroll
        for (int p = 0; p < 4; p++) ac[p] = make_float2(0.f, 0.f);
#pragma unroll
        for (int j = 0; j < 16; j++) {
            float2 m = make2(g_Meff[j * 256 + t]);
            float4 e0 = *(const float4*)&s_efT[j][0];
            float4 e1 = *(const float4*)&s_efT[j][4];
            ac[0] = ffma2(f2(e0.x, e0.y), m, ac[0]);
            ac[1] = ffma2(f2(e0.z, e0.w), m, ac[1]);
            ac[2] = ffma2(f2(e1.x, e1.y), m, ac[2]);
            ac[3] = ffma2(f2(e1.z, e1.w), m, ac[3]);
        }
#pragma unroll
        for (int p = 0; p < 4; p++) {
            s_wmm[2 * p][t]     = ac[p].x;
            s_wmm[2 * p + 1][t] = ac[p].y;
        }
    }
    if (t < 8) {
        int el = t;
        int e = s_e[el], sd = s_send[el];
        s_sh0[el] = ea[(size_t)e * 16];
        float q = 0.f;
#pragma unroll
        for (int j = 0; j < 8; j++) q += ef[e * 8 + j] * Wd[j];
        q *= 0.35355339059327373f;
        g_dens[p0 + el] = tanhf(q * q);
        s_mm0[el] = mma[sd * 4];
        g_mmsh3[(p0 + el) * 3 + 0] = mma[sd * 4 + 1];
        g_mmsh3[(p0 + el) * 3 + 1] = mma[sd * 4 + 2];
        g_mmsh3[(p0 + el) * 3 + 2] = mma[sd * 4 + 3];
    }
    __syncthreads();
#pragma unroll
    for (int r = 0; r < 4; r++) {
        int pair = t + 256 * r;
        int el = pair >> 7, u = pair & 127;
        int p = p0 + el;
        float xj = g_x[s_send[el] * 128 + u];
        float4 w4 = *(const float4*)&s_w4[el][u * 4];
        float pre = w4.x * xj * s_sh0[el];
        float wm0 = s_wmm[el][u * 2 + 0] * pre;
        float wm1 = s_wmm[el][u * 2 + 1] * pre;
        float gate = wm0 * xj * s_mm0[el];
        size_t b = (size_t)p * 128 + u;
        g_gate[b] = gate;
        g_wm1x[b] = wm1 * xj;
        float gx = gate * xj;
        float4 A;
        A.x = w4.x * gx; A.y = w4.y * gx; A.z = w4.z * gx; A.w = w4.w * gx;
        reinterpret_cast<float4*>(g_A)[b] = A;
    }
}

// ---------------- launch 5: aggregation; phase-2 now m-paired FFMA2 ----------------
__global__ void __launch_bounds__(128) k_agg(const float* __restrict__ ea,
                                             const float* __restrict__ Wlin,
                                             const float* __restrict__ Wmlin)
{
    __shared__ float s_msg[4][128 * 16];
    __shared__ float s_mm[4][128 * 4];
    __shared__ float s_d[4];
    int u = threadIdx.x;
    int n0 = blockIdx.x * 4;

    for (int tn = 0; tn < 4; tn++) {
        int n = n0 + tn;
        float acc[16], am[4];
#pragma unroll
        for (int m = 0; m < 16; m++) acc[m] = 0.f;
#pragma unroll
        for (int j = 0; j < 4; j++) am[j] = 0.f;
        float dl = 0.f;
        int pb = g_off[n], pe = g_off[n + 1];
        for (int p = pb; p < pe; p++) {
            int e = g_perm[p];
            size_t b = (size_t)p * 128 + u;
            float4 A = reinterpret_cast<const float4*>(g_A)[b];
            float gate = g_gate[b];
            float wx = g_wm1x[b];
            const float* sh = ea + (size_t)e * 16;
            acc[0] += A.x * __ldg(sh + 0);
            acc[1] += A.y * __ldg(sh + 1);
            acc[2] += A.y * __ldg(sh + 2);
            acc[3] += A.y * __ldg(sh + 3);
#pragma unroll
            for (int m = 4; m < 9; m++) acc[m] += A.z * __ldg(sh + m);
#pragma unroll
            for (int m = 9; m < 16; m++) acc[m] += A.w * __ldg(sh + m);
            am[0] += gate;
            am[1] += wx * __ldg(&g_mmsh3[p * 3 + 0]);
            am[2] += wx * __ldg(&g_mmsh3[p * 3 + 1]);
            am[3] += wx * __ldg(&g_mmsh3[p * 3 + 2]);
            dl += __ldg(&g_dens[p]);
        }
#pragma unroll
        for (int m = 0; m < 16; m++) s_msg[tn][u * 16 + m] = acc[m];
#pragma unroll
        for (int j = 0; j < 4; j++) s_mm[tn][u * 4 + j] = am[j];
        if (u == 0) s_d[tn] = dl;
    }
    __syncthreads();

    int v = u;
    float2 lin2[4][8];
    float2 lmm2[4][2];
#pragma unroll
    for (int tn = 0; tn < 4; tn++) {
#pragma unroll
        for (int k = 0; k < 8; k++) lin2[tn][k] = make_float2(0.f, 0.f);
        lmm2[tn][0] = make_float2(0.f, 0.f);
        lmm2[tn][1] = make_float2(0.f, 0.f);
    }
    for (int uu = 0; uu < 128; uu++) {
        float w0 = Wlin[(0 * 128 + uu) * 128 + v];
        float w1 = Wlin[(1 * 128 + uu) * 128 + v];
        float w2 = Wlin[(2 * 128 + uu) * 128 + v];
        float w3 = Wlin[(3 * 128 + uu) * 128 + v];
        float m0 = Wmlin[(0 * 128 + uu) * 128 + v];
        float m1 = Wmlin[(1 * 128 + uu) * 128 + v];
        float2 p01 = f2(w0, w1), p11 = make2(w1), p22 = make2(w2);
        float2 p23 = f2(w2, w3), p33 = make2(w3);
        float2 q01 = f2(m0, m1), q11 = make2(m1);
#pragma unroll
        for (int tn = 0; tn < 4; tn++) {
            const float4* mp = reinterpret_cast<const float4*>(&s_msg[tn][uu * 16]);
            float4 c0 = mp[0], c1 = mp[1], c2 = mp[2], c3 = mp[3];
            lin2[tn][0] = ffma2(f2(c0.x, c0.y), p01, lin2[tn][0]);
            lin2[tn][1] = ffma2(f2(c0.z, c0.w), p11, lin2[tn][1]);
            lin2[tn][2] = ffma2(f2(c1.x, c1.y), p22, lin2[tn][2]);
            lin2[tn][3] = ffma2(f2(c1.z, c1.w), p22, lin2[tn][3]);
            lin2[tn][4] = ffma2(f2(c2.x, c2.y), p23, lin2[tn][4]);
            lin2[tn][5] = ffma2(f2(c2.z, c2.w), p33, lin2[tn][5]);
            lin2[tn][6] = ffma2(f2(c3.x, c3.y), p33, lin2[tn][6]);
            lin2[tn][7] = ffma2(f2(c3.z, c3.w), p33, lin2[tn][7]);
            float4 mq = reinterpret_cast<const float4*>(&s_mm[tn][uu * 4])[0];
            lmm2[tn][0] = ffma2(f2(mq.x, mq.y), q01, lmm2[tn][0]);
            lmm2[tn][1] = ffma2(f2(mq.z, mq.w), q11, lmm2[tn][1]);
        }
    }
    const float sL = 0.08838834764831845f;
#pragma unroll
    for (int tn = 0; tn < 4; tn++) {
        float inv = sL / (s_d[tn] + 1.0f);
        size_t ob = ((size_t)(n0 + tn) * 128 + v) * 16;
#pragma unroll
        for (int k = 0; k < 8; k++) {
            g_msglin[ob + 2 * k]     = lin2[tn][k].x * inv;
            g_msglin[ob + 2 * k + 1] = lin2[tn][k].y * inv;
        }
        float im = sL * 0.05f;
        size_t ob2 = ((size_t)(n0 + tn) * 128 + v) * 4;
        g_mmlin[ob2 + 0] = lmm2[tn][0].x * im;
        g_mmlin[ob2 + 1] = lmm2[tn][0].y * im;
        g_mmlin[ob2 + 2] = lmm2[tn][1].x * im;
        g_mmlin[ob2 + 3] = lmm2[tn][1].y * im;
    }
}

// ---------------- launch 6: mm skip path, NT=8, z-paired weights (R10 proven) ----------------
__global__ void __launch_bounds__(128) k_skipmm(const float* __restrict__ na,
                                                float* __restrict__ out)
{
    __shared__ float s_mml[8][512];
    int v = threadIdx.x;
    int n0 = blockIdx.x * 8;

    for (int tn = 0; tn < 8; tn++) {
        const float4* s2 = reinterpret_cast<const float4*>(&g_mmlin[(size_t)(n0 + tn) * 512]);
        reinterpret_cast<float4*>(s_mml[tn])[v] = s2[v];
    }
    float2 at2[8][5];
#pragma unroll
    for (int tn = 0; tn < 8; tn++)
#pragma unroll
        for (int k = 0; k < 5; k++)
            at2[tn][k] = f2(__ldg(&na[(n0 + tn) * 10 + 2 * k]),
                            __ldg(&na[(n0 + tn) * 10 + 2 * k + 1]));
    __syncthreads();

    float a2[8][4];
#pragma unroll
    for (int tn = 0; tn < 8; tn++)
#pragma unroll
        for (int j = 0; j < 4; j++) a2[tn][j] = 0.f;

    for (int uu = 0; uu < 128; uu++) {
        float t2[8][2];
#pragma unroll
        for (int l = 0; l < 2; l++) {
            const float2* W = &g_Wmp[((l * 128 + uu) * 5) * 128 + v];
            float2 w0 = __ldg(W), w1 = __ldg(W + 128), w2 = __ldg(W + 256);
            float2 w3 = __ldg(W + 384), w4 = __ldg(W + 512);
#pragma unroll
            for (int tn = 0; tn < 8; tn++) {
                float2 s = make_float2(0.f, 0.f);
                s = ffma2(at2[tn][0], w0, s);
                s = ffma2(at2[tn][1], w1, s);
                s = ffma2(at2[tn][2], w2, s);
                s = ffma2(at2[tn][3], w3, s);
                s = ffma2(at2[tn][4], w4, s);
                t2[tn][l] = s.x + s.y;
            }
        }
#pragma unroll
        for (int tn = 0; tn < 8; tn++) {
            float4 mq = reinterpret_cast<const float4*>(&s_mml[tn][uu * 4])[0];
            a2[tn][0] += mq.x * t2[tn][0];
            a2[tn][1] += mq.y * t2[tn][1];
            a2[tn][2] += mq.z * t2[tn][1];
            a2[tn][3] += mq.w * t2[tn][1];
        }
    }
    const float sc = 0.02795084971874737f;  // 1/sqrt(1280)
#pragma unroll
    for (int tn = 0; tn < 8; tn++) {
        size_t ob2 = (size_t)NN * 2048 + ((size_t)(n0 + tn) * 128 + v) * 16;
#pragma unroll
        for (int m = 0; m < 4; m++) out[ob2 + m] = a2[tn][m] * sc;
#pragma unroll
        for (int m = 4; m < 16; m++) out[ob2 + m] = 0.f;  // mm l=2,3 have no path
    }
}

// ---------------- launch 7: main skip TP, NT=4, z-paired tt + m-paired a1 ----------------
__global__ void __launch_bounds__(128) k_skip(const float* __restrict__ na,
                                              float* __restrict__ out)
{
    __shared__ float s_ml[4][2048];
    int v = threadIdx.x;
    int n0 = blockIdx.x * 4;

    for (int tn = 0; tn < 4; tn++) {
        const float4* src = reinterpret_cast<const float4*>(&g_msglin[(size_t)(n0 + tn) * 2048]);
        float4* dst = reinterpret_cast<float4*>(s_ml[tn]);
        for (int i = v; i < 512; i += 128) dst[i] = src[i];
    }
    float2 at2[4][5];
#pragma unroll
    for (int tn = 0; tn < 4; tn++)
#pragma unroll
        for (int k = 0; k < 5; k++)
            at2[tn][k] = f2(__ldg(&na[(n0 + tn) * 10 + 2 * k]),
                            __ldg(&na[(n0 + tn) * 10 + 2 * k + 1]));
    __syncthreads();

    float2 a1p[4][8];
#pragma unroll
    for (int tn = 0; tn < 4; tn++)
#pragma unroll
        for (int k = 0; k < 8; k++) a1p[tn][k] = make_float2(0.f, 0.f);

    for (int uu = 0; uu < 128; uu++) {
        float tt[4][4];
#pragma unroll
        for (int l = 0; l < 4; l++) {
            const float2* W = &g_Wp[((l * 128 + uu) * 5) * 128 + v];
            float2 w0 = __ldg(W), w1 = __ldg(W + 128), w2 = __ldg(W + 256);
            float2 w3 = __ldg(W + 384), w4 = __ldg(W + 512);
#pragma unroll
            for (int tn = 0; tn < 4; tn++) {
                float2 s = make_float2(0.f, 0.f);
                s = ffma2(at2[tn][0], w0, s);
                s = ffma2(at2[tn][1], w1, s);
                s = ffma2(at2[tn][2], w2, s);
                s = ffma2(at2[tn][3], w3, s);
                s = ffma2(at2[tn][4], w4, s);
                tt[tn][l] = s.x + s.y;
            }
        }
#pragma unroll
        for (int tn = 0; tn < 4; tn++) {
            float2 t01 = f2(tt[tn][0], tt[tn][1]);
            float2 t11 = make2(tt[tn][1]);
            float2 t22 = make2(tt[tn][2]);
            float2 t23 = f2(tt[tn][2], tt[tn][3]);
            float2 t33 = make2(tt[tn][3]);
            const float4* mp = reinterpret_cast<const float4*>(&s_ml[tn][uu * 16]);
            float4 c0 = mp[0], c1 = mp[1], c2 = mp[2], c3 = mp[3];
            a1p[tn][0] = ffma2(f2(c0.x, c0.y), t01, a1p[tn][0]);
            a1p[tn][1] = ffma2(f2(c0.z, c0.w), t11, a1p[tn][1]);
            a1p[tn][2] = ffma2(f2(c1.x, c1.y), t22, a1p[tn][2]);
            a1p[tn][3] = ffma2(f2(c1.z, c1.w), t22, a1p[tn][3]);
            a1p[tn][4] = ffma2(f2(c2.x, c2.y), t23, a1p[tn][4]);
            a1p[tn][5] = ffma2(f2(c2.z, c2.w), t33, a1p[tn][5]);
            a1p[tn][6] = ffma2(f2(c3.x, c3.y), t33, a1p[tn][6]);
            a1p[tn][7] = ffma2(f2(c3.z, c3.w), t33, a1p[tn][7]);
        }
    }
    const float sc = 0.02795084971874737f;  // 1/sqrt(1280)
#pragma unroll
    for (int tn = 0; tn < 4; tn++) {
        size_t ob = ((size_t)(n0 + tn) * 128 + v) * 16;
#pragma unroll
        for (int k = 0; k < 8; k++) {
            out[ob + 2 * k]     = a1p[tn][k].x * sc;
            out[ob + 2 * k + 1] = a1p[tn][k].y * sc;
        }
    }
}

// ---------------- host ----------------
extern "C" void kernel_launch(void* const* d_in, const int* in_sizes, int n_in,
                              void* d_out, int out_size)
{
    const int* ei;
    int wi;
    if (in_sizes[6] == 2 * NE) { ei = (const int*)d_in[6]; wi = 7; }
    else                       { ei = (const int*)d_in[n_in - 1]; wi = 6; }

    const float* na   = (const float*)d_in[0];
    const float* nf   = (const float*)d_in[1];
    const float* ea   = (const float*)d_in[2];
    const float* ef   = (const float*)d_in[3];
    const float* mmi  = (const float*)d_in[4];
    const float* mma  = (const float*)d_in[5];
    const float* Wup  = (const float*)d_in[wi + 0];
    const float* W1   = (const float*)d_in[wi + 1];
    const float* W2   = (const float*)d_in[wi + 2];
    const float* W3   = (const float*)d_in[wi + 3];
    const float* W4   = (const float*)d_in[wi + 4];
    const float* M1   = (const float*)d_in[wi + 5];
    const float* M2   = (const float*)d_in[wi + 6];
    const float* M3   = (const float*)d_in[wi + 7];
    const float* M4   = (const float*)d_in[wi + 8];
    const float* Wd   = (const float*)d_in[wi + 9];
    const float* Wlin = (const float*)d_in[wi + 10];
    const float* Wmlin= (const float*)d_in[wi + 11];
    const float* Wsk  = (const float*)d_in[wi + 12];
    const float* Wmsk = (const float*)d_in[wi + 13];
    float* out = (float*)d_out;

    k_hx<<<NN, 128>>>(nf, Wup, ei, Wsk, Wmsk);                    // 1: x + hist + weight pack
    k_scanmeff<<<1, 1024>>>(M1, M2, M3, M4);                      // 2
    k_scatter<<<(NE + 255) / 256, 256>>>(ei);                     // 3
    k_edge<<<NE / 8, 256>>>(W1, W2, W3, W4, ea, ef, mmi, mma, Wd, ei);  // 4 <- ncu slot
    k_agg<<<NN / 4, 128>>>(ea, Wlin, Wmlin);                      // 5
    k_skipmm<<<NN / 8, 128>>>(na, out);                           // 6
    k_skip<<<NN / 4, 128>>>(na, out);                             // 7
}

// round 15
// speedup vs baseline: 1.2021x; 1.0252x over previous
#include <cuda_runtime.h>
#include <cuda_fp16.h>
#include <math.h>
#include <stdint.h>

#define NN 5000
#define NE 100000
#define MULC 128

// ---------------- device scratch (static, no allocation) ----------------
__device__ float   g_x[NN * MULC];
__device__ float   g_Meff[16 * 256];
__device__ int     g_cnt[NN];
__device__ int     g_cur[NN];
__device__ int     g_off[NN + 1];
__device__ int     g_perm[NE];
__device__ __half2 g_Ah[(size_t)NE * MULC * 2];   // A[l]*2^-8 as 4 halves per (pos,u)
__device__ __half2 g_gwh[(size_t)NE * MULC];      // {gate, wm1x}*2^-8
__device__ float   g_mmsh3[NE * 3];
__device__ float   g_dens[NE];
__device__ float   g_msglin[NN * MULC * 16];
__device__ float   g_mmlin[NN * MULC * 4];
__device__ float2  g_Wp[4 * 128 * 5 * 128];   // Wsk z-paired: ((l*128+uu)*5+zp)*128+v
__device__ float2  g_Wmp[2 * 128 * 5 * 128];  // Wmsk l=0,1 z-paired

__device__ __forceinline__ float silu_f(float x) { return x / (1.0f + __expf(-x)); }
__device__ __forceinline__ float2 f2(float a, float b) { return make_float2(a, b); }
__device__ __forceinline__ float2 make2(float x) { return make_float2(x, x); }
__device__ __forceinline__ float2 ffma2(float2 a, float2 b, float2 c) {
    unsigned long long ra = *reinterpret_cast<unsigned long long*>(&a);
    unsigned long long rb = *reinterpret_cast<unsigned long long*>(&b);
    unsigned long long rc = *reinterpret_cast<unsigned long long*>(&c);
    unsigned long long rd;
    asm("fma.rn.f32x2 %0, %1, %2, %3;" : "=l"(rd) : "l"(ra), "l"(rb), "l"(rc));
    return *reinterpret_cast<float2*>(&rd);
}

// ---------------- launch 1: x = nf@Wup/sqrt(128) + receiver histogram + weight z-pair pack ----
__global__ void __launch_bounds__(128) k_hx(const float* __restrict__ nf,
                                            const float* __restrict__ Wup,
                                            const int* __restrict__ ei,
                                            const float* __restrict__ Wsk,
                                            const float* __restrict__ Wmsk) {
    __shared__ float s[128];
    int n = blockIdx.x, t = threadIdx.x;
    s[t] = nf[n * 128 + t];
    __syncthreads();
    float acc = 0.f;
#pragma unroll 8
    for (int u = 0; u < 128; u++) acc += s[u] * Wup[u * 128 + t];
    g_x[n * 128 + t] = acc * 0.08838834764831845f;
    int gid = n * 128 + t;
    if (gid < NE) atomicAdd(&g_cnt[ei[NE + gid]], 1);
    const int T1 = 4 * 128 * 5 * 128;
    const int T2 = 2 * 128 * 5 * 128;
    if (gid < T1) {
        int v = gid & 127;
        int zp = (gid >> 7) % 5;
        int lu = gid / (5 * 128);
        const float* b = Wsk + ((size_t)lu * 10 + 2 * zp) * 128 + v;
        g_Wp[gid] = f2(b[0], b[128]);
    } else if (gid < T1 + T2) {
        int j = gid - T1;
        int v = j & 127;
        int zp = (j >> 7) % 5;
        int lu = j / (5 * 128);
        const float* b = Wmsk + ((size_t)lu * 10 + 2 * zp) * 128 + v;
        g_Wmp[j] = f2(b[0], b[128]);
    }
}

// ---------------- launch 2: Meff + CSR scan + self-restore zeroing (1 block) ----------------
__global__ void __launch_bounds__(1024) k_scanmeff(
    const float* __restrict__ M1, const float* __restrict__ M2,
    const float* __restrict__ M3, const float* __restrict__ M4) {
    __shared__ float T1[16 * 64];
    __shared__ float T2[16 * 64];
    __shared__ int   s[1024];
    int t = threadIdx.x;
    for (int idx = t; idx < 16 * 64; idx += 1024) {
        int a = idx >> 6, k = idx & 63;
        float acc = 0.f;
        for (int b = 0; b < 64; b++) acc += M1[a * 64 + b] * M2[b * 64 + k];
        T1[idx] = acc;
    }
    __syncthreads();
    for (int idx = t; idx < 16 * 64; idx += 1024) {
        int a = idx >> 6, k = idx & 63;
        float acc = 0.f;
        for (int b = 0; b < 64; b++) acc += T1[a * 64 + b] * M3[b * 64 + k];
        T2[idx] = acc;
    }
    __syncthreads();
    for (int idx = t; idx < 16 * 256; idx += 1024) {
        int a = idx >> 8, c = idx & 255;
        float acc = 0.f;
        for (int b = 0; b < 64; b++) acc += T2[a * 64 + b] * M4[b * 256 + c];
        g_Meff[idx] = acc * 4.8828125e-4f;
    }
    int carry = 0;
    for (int base = 0; base < NN; base += 1024) {
        int i = base + t;
        int c = (i < NN) ? g_cnt[i] : 0;
        s[t] = c;
        __syncthreads();
        for (int d = 1; d < 1024; d <<= 1) {
            int v = (t >= d) ? s[t - d] : 0;
            __syncthreads();
            s[t] += v;
            __syncthreads();
        }
        if (i < NN) g_off[i] = carry + s[t] - c;
        carry += s[1023];
        __syncthreads();
    }
    if (t == 0) g_off[NN] = NE;
    __syncthreads();
    for (int i = t; i < NN; i += 1024) { g_cnt[i] = 0; g_cur[i] = 0; }
}

// ---------------- launch 3: scatter edges into CSR order ----------------
__global__ void __launch_bounds__(256) k_scatter(const int* __restrict__ ei) {
    int e = blockIdx.x * blockDim.x + threadIdx.x;
    if (e < NE) {
        int r = ei[NE + e];
        int k = atomicAdd(&g_cur[r], 1);
        g_perm[g_off[r] + k] = e;
    }
}

// ---------------- launch 4: edge kernel (R11/R12 math; epilogue stores fp16*2^-8) ----------------
__global__ void __launch_bounds__(256) k_edge(
    const float* __restrict__ W1, const float* __restrict__ W2,
    const float* __restrict__ W3, const float* __restrict__ W4,
    const float* __restrict__ ea, const float* __restrict__ ef,
    const float* __restrict__ mmi, const float* __restrict__ mma,
    const float* __restrict__ Wd, const int* __restrict__ ei)
{
    __shared__ float s_efT[16][8];     // [j][el]
    __shared__ float s_h1T[64][12];    // [j][el], pad 12 (16B-aligned rows)
    __shared__ float s_h2T[64][12];
    __shared__ float s_h3T[64][12];
    __shared__ float s_w4[8][512];
    __shared__ float s_wmm[8][256];
    __shared__ int   s_e[8], s_send[8];
    __shared__ float s_sh0[8], s_mm0[8];

    int t = threadIdx.x;
    int p0 = blockIdx.x * 8;

    if (t < 8) {
        int e = g_perm[p0 + t];
        s_e[t] = e;
        s_send[t] = ei[e];
    }
    __syncthreads();
    if (t < 128) {
        int el = t >> 4, j = t & 15;
        int e = s_e[el], sd = s_send[el];
        s_efT[j][el] = (j < 8) ? ef[e * 8 + j] : mmi[sd * 8 + (j - 8)];
    }
    __syncthreads();

    int i = t & 63;    // output neuron
    int ep = t >> 6;   // edge-pair 0..3
    {
        float2 a = make_float2(0.f, 0.f);
#pragma unroll
        for (int j = 0; j < 16; j++)
            a = ffma2(*(const float2*)&s_efT[j][2 * ep], make2(W1[j * 64 + i]), a);
        *(float2*)&s_h1T[i][2 * ep] = f2(silu_f(a.x * 0.25f), silu_f(a.y * 0.25f));
    }
    __syncthreads();
    {
        float2 a = make_float2(0.f, 0.f);
#pragma unroll 8
        for (int j = 0; j < 64; j++)
            a = ffma2(*(const float2*)&s_h1T[j][2 * ep], make2(W2[j * 64 + i]), a);
        *(float2*)&s_h2T[i][2 * ep] = f2(silu_f(a.x * 0.125f), silu_f(a.y * 0.125f));
    }
    __syncthreads();
    {
        float2 a = make_float2(0.f, 0.f);
#pragma unroll 8
        for (int j = 0; j < 64; j++)
            a = ffma2(*(const float2*)&s_h2T[j][2 * ep], make2(W3[j * 64 + i]), a);
        *(float2*)&s_h3T[i][2 * ep] = f2(silu_f(a.x * 0.125f), silu_f(a.y * 0.125f));
    }
    __syncthreads();
    {
        float2 a0[4], a1[4];
#pragma unroll
        for (int p = 0; p < 4; p++) { a0[p] = make_float2(0.f, 0.f); a1[p] = make_float2(0.f, 0.f); }
#pragma unroll 4
        for (int j = 0; j < 64; j++) {
            float2 w = *(const float2*)&W4[j * 512 + 2 * t];
            float4 h0 = *(const float4*)&s_h3T[j][0];
            float4 h1 = *(const float4*)&s_h3T[j][4];
            float2 hp0 = f2(h0.x, h0.y), hp1 = f2(h0.z, h0.w);
            float2 hp2 = f2(h1.x, h1.y), hp3 = f2(h1.z, h1.w);
            float2 w0 = make2(w.x), w1 = make2(w.y);
            a0[0] = ffma2(hp0, w0, a0[0]); a1[0] = ffma2(hp0, w1, a1[0]);
            a0[1] = ffma2(hp1, w0, a0[1]); a1[1] = ffma2(hp1, w1, a1[1]);
            a0[2] = ffma2(hp2, w0, a0[2]); a1[2] = ffma2(hp2, w1, a1[2]);
            a0[3] = ffma2(hp3, w0, a0[3]); a1[3] = ffma2(hp3, w1, a1[3]);
        }
#pragma unroll
        for (int p = 0; p < 4; p++) {
            s_w4[2 * p][2 * t]         = a0[p].x * 0.125f;
            s_w4[2 * p + 1][2 * t]     = a0[p].y * 0.125f;
            s_w4[2 * p][2 * t + 1]     = a1[p].x * 0.125f;
            s_w4[2 * p + 1][2 * t + 1] = a1[p].y * 0.125f;
        }
    }
    {
        float2 ac[4];
#pragma unroll
        for (int p = 0; p < 4; p++) ac[p] = make_float2(0.f, 0.f);
#pragma unroll
        for (int j = 0; j < 16; j++) {
            float2 m = make2(g_Meff[j * 256 + t]);
            float4 e0 = *(const float4*)&s_efT[j][0];
            float4 e1 = *(const float4*)&s_efT[j][4];
            ac[0] = ffma2(f2(e0.x, e0.y), m, ac[0]);
            ac[1] = ffma2(f2(e0.z, e0.w), m, ac[1]);
            ac[2] = ffma2(f2(e1.x, e1.y), m, ac[2]);
            ac[3] = ffma2(f2(e1.z, e1.w), m, ac[3]);
        }
#pragma unroll
        for (int p = 0; p < 4; p++) {
            s_wmm[2 * p][t]     = ac[p].x;
            s_wmm[2 * p + 1][t] = ac[p].y;
        }
    }
    if (t < 8) {
        int el = t;
        int e = s_e[el], sd = s_send[el];
        s_sh0[el] = ea[(size_t)e * 16];
        float q = 0.f;
#pragma unroll
        for (int j = 0; j < 8; j++) q += ef[e * 8 + j] * Wd[j];
        q *= 0.35355339059327373f;
        g_dens[p0 + el] = tanhf(q * q);
        s_mm0[el] = mma[sd * 4];
        g_mmsh3[(p0 + el) * 3 + 0] = mma[sd * 4 + 1];
        g_mmsh3[(p0 + el) * 3 + 1] = mma[sd * 4 + 2];
        g_mmsh3[(p0 + el) * 3 + 2] = mma[sd * 4 + 3];
    }
    __syncthreads();
    const float S = 0.00390625f;  // 2^-8 range guard for fp16
#pragma unroll
    for (int r = 0; r < 4; r++) {
        int pair = t + 256 * r;
        int el = pair >> 7, u = pair & 127;
        int p = p0 + el;
        float xj = g_x[s_send[el] * 128 + u];
        float4 w4 = *(const float4*)&s_w4[el][u * 4];
        float pre = w4.x * xj * s_sh0[el];
        float wm0 = s_wmm[el][u * 2 + 0] * pre;
        float wm1 = s_wmm[el][u * 2 + 1] * pre;
        float gate = wm0 * xj * s_mm0[el];
        size_t b = (size_t)p * 128 + u;
        g_gwh[b] = __floats2half2_rn(gate * S, wm1 * xj * S);
        float gx = gate * xj * S;
        __half2 h01 = __floats2half2_rn(w4.x * gx, w4.y * gx);
        __half2 h23 = __floats2half2_rn(w4.z * gx, w4.w * gx);
        uint2 raw;
        raw.x = *reinterpret_cast<unsigned*>(&h01);
        raw.y = *reinterpret_cast<unsigned*>(&h23);
        *reinterpret_cast<uint2*>(&g_Ah[2 * b]) = raw;
    }
}

// ---------------- launch 5: aggregation; phase-1 reads fp16 scratch; phase-2 m-paired FFMA2 ----
__global__ void __launch_bounds__(128) k_agg(const float* __restrict__ ea,
                                             const float* __restrict__ Wlin,
                                             const float* __restrict__ Wmlin)
{
    __shared__ float s_msg[4][128 * 16];
    __shared__ float s_mm[4][128 * 4];
    __shared__ float s_d[4];
    int u = threadIdx.x;
    int n0 = blockIdx.x * 4;

    for (int tn = 0; tn < 4; tn++) {
        int n = n0 + tn;
        float acc[16], am[4];
#pragma unroll
        for (int m = 0; m < 16; m++) acc[m] = 0.f;
#pragma unroll
        for (int j = 0; j < 4; j++) am[j] = 0.f;
        float dl = 0.f;
        int pb = g_off[n], pe = g_off[n + 1];
        for (int p = pb; p < pe; p++) {
            int e = g_perm[p];
            size_t b = (size_t)p * 128 + u;
            uint2 raw = *reinterpret_cast<const uint2*>(&g_Ah[2 * b]);
            float2 A01 = __half22float2(*reinterpret_cast<__half2*>(&raw.x));
            float2 A23 = __half22float2(*reinterpret_cast<__half2*>(&raw.y));
            float2 gw  = __half22float2(g_gwh[b]);
            const float* sh = ea + (size_t)e * 16;
            acc[0] += A01.x * __ldg(sh + 0);
            acc[1] += A01.y * __ldg(sh + 1);
            acc[2] += A01.y * __ldg(sh + 2);
            acc[3] += A01.y * __ldg(sh + 3);
#pragma unroll
            for (int m = 4; m < 9; m++) acc[m] += A23.x * __ldg(sh + m);
#pragma unroll
            for (int m = 9; m < 16; m++) acc[m] += A23.y * __ldg(sh + m);
            am[0] += gw.x;
            am[1] += gw.y * __ldg(&g_mmsh3[p * 3 + 0]);
            am[2] += gw.y * __ldg(&g_mmsh3[p * 3 + 1]);
            am[3] += gw.y * __ldg(&g_mmsh3[p * 3 + 2]);
            dl += __ldg(&g_dens[p]);
        }
#pragma unroll
        for (int m = 0; m < 16; m++) s_msg[tn][u * 16 + m] = acc[m];
#pragma unroll
        for (int j = 0; j < 4; j++) s_mm[tn][u * 4 + j] = am[j];
        if (u == 0) s_d[tn] = dl;
    }
    __syncthreads();

    int v = u;
    float2 lin2[4][8];
    float2 lmm2[4][2];
#pragma unroll
    for (int tn = 0; tn < 4; tn++) {
#pragma unroll
        for (int k = 0; k < 8; k++) lin2[tn][k] = make_float2(0.f, 0.f);
        lmm2[tn][0] = make_float2(0.f, 0.f);
        lmm2[tn][1] = make_float2(0.f, 0.f);
    }
    for (int uu = 0; uu < 128; uu++) {
        float w0 = Wlin[(0 * 128 + uu) * 128 + v];
        float w1 = Wlin[(1 * 128 + uu) * 128 + v];
        float w2 = Wlin[(2 * 128 + uu) * 128 + v];
        float w3 = Wlin[(3 * 128 + uu) * 128 + v];
        float m0 = Wmlin[(0 * 128 + uu) * 128 + v];
        float m1 = Wmlin[(1 * 128 + uu) * 128 + v];
        float2 p01 = f2(w0, w1), p11 = make2(w1), p22 = make2(w2);
        float2 p23 = f2(w2, w3), p33 = make2(w3);
        float2 q01 = f2(m0, m1), q11 = make2(m1);
#pragma unroll
        for (int tn = 0; tn < 4; tn++) {
            const float4* mp = reinterpret_cast<const float4*>(&s_msg[tn][uu * 16]);
            float4 c0 = mp[0], c1 = mp[1], c2 = mp[2], c3 = mp[3];
            lin2[tn][0] = ffma2(f2(c0.x, c0.y), p01, lin2[tn][0]);
            lin2[tn][1] = ffma2(f2(c0.z, c0.w), p11, lin2[tn][1]);
            lin2[tn][2] = ffma2(f2(c1.x, c1.y), p22, lin2[tn][2]);
            lin2[tn][3] = ffma2(f2(c1.z, c1.w), p22, lin2[tn][3]);
            lin2[tn][4] = ffma2(f2(c2.x, c2.y), p23, lin2[tn][4]);
            lin2[tn][5] = ffma2(f2(c2.z, c2.w), p33, lin2[tn][5]);
            lin2[tn][6] = ffma2(f2(c3.x, c3.y), p33, lin2[tn][6]);
            lin2[tn][7] = ffma2(f2(c3.z, c3.w), p33, lin2[tn][7]);
            float4 mq = reinterpret_cast<const float4*>(&s_mm[tn][uu * 4])[0];
            lmm2[tn][0] = ffma2(f2(mq.x, mq.y), q01, lmm2[tn][0]);
            lmm2[tn][1] = ffma2(f2(mq.z, mq.w), q11, lmm2[tn][1]);
        }
    }
    const float sL = 0.08838834764831845f * 256.0f;  // undo 2^-8 scratch scale
#pragma unroll
    for (int tn = 0; tn < 4; tn++) {
        float inv = sL / (s_d[tn] + 1.0f);
        size_t ob = ((size_t)(n0 + tn) * 128 + v) * 16;
#pragma unroll
        for (int k = 0; k < 8; k++) {
            g_msglin[ob + 2 * k]     = lin2[tn][k].x * inv;
            g_msglin[ob + 2 * k + 1] = lin2[tn][k].y * inv;
        }
        float im = sL * 0.05f;
        size_t ob2 = ((size_t)(n0 + tn) * 128 + v) * 4;
        g_mmlin[ob2 + 0] = lmm2[tn][0].x * im;
        g_mmlin[ob2 + 1] = lmm2[tn][0].y * im;
        g_mmlin[ob2 + 2] = lmm2[tn][1].x * im;
        g_mmlin[ob2 + 3] = lmm2[tn][1].y * im;
    }
}

// ---------------- launch 6: mm skip path, NT=8, z-paired weights (R10 proven) ----------------
__global__ void __launch_bounds__(128) k_skipmm(const float* __restrict__ na,
                                                float* __restrict__ out)
{
    __shared__ float s_mml[8][512];
    int v = threadIdx.x;
    int n0 = blockIdx.x * 8;

    for (int tn = 0; tn < 8; tn++) {
        const float4* s2 = reinterpret_cast<const float4*>(&g_mmlin[(size_t)(n0 + tn) * 512]);
        reinterpret_cast<float4*>(s_mml[tn])[v] = s2[v];
    }
    float2 at2[8][5];
#pragma unroll
    for (int tn = 0; tn < 8; tn++)
#pragma unroll
        for (int k = 0; k < 5; k++)
            at2[tn][k] = f2(__ldg(&na[(n0 + tn) * 10 + 2 * k]),
                            __ldg(&na[(n0 + tn) * 10 + 2 * k + 1]));
    __syncthreads();

    float a2[8][4];
#pragma unroll
    for (int tn = 0; tn < 8; tn++)
#pragma unroll
        for (int j = 0; j < 4; j++) a2[tn][j] = 0.f;

    for (int uu = 0; uu < 128; uu++) {
        float t2[8][2];
#pragma unroll
        for (int l = 0; l < 2; l++) {
            const float2* W = &g_Wmp[((l * 128 + uu) * 5) * 128 + v];
            float2 w0 = __ldg(W), w1 = __ldg(W + 128), w2 = __ldg(W + 256);
            float2 w3 = __ldg(W + 384), w4 = __ldg(W + 512);
#pragma unroll
            for (int tn = 0; tn < 8; tn++) {
                float2 s = make_float2(0.f, 0.f);
                s = ffma2(at2[tn][0], w0, s);
                s = ffma2(at2[tn][1], w1, s);
                s = ffma2(at2[tn][2], w2, s);
                s = ffma2(at2[tn][3], w3, s);
                s = ffma2(at2[tn][4], w4, s);
                t2[tn][l] = s.x + s.y;
            }
        }
#pragma unroll
        for (int tn = 0; tn < 8; tn++) {
            float4 mq = reinterpret_cast<const float4*>(&s_mml[tn][uu * 4])[0];
            a2[tn][0] += mq.x * t2[tn][0];
            a2[tn][1] += mq.y * t2[tn][1];
            a2[tn][2] += mq.z * t2[tn][1];
            a2[tn][3] += mq.w * t2[tn][1];
        }
    }
    const float sc = 0.02795084971874737f;  // 1/sqrt(1280)
#pragma unroll
    for (int tn = 0; tn < 8; tn++) {
        size_t ob2 = (size_t)NN * 2048 + ((size_t)(n0 + tn) * 128 + v) * 16;
#pragma unroll
        for (int m = 0; m < 4; m++) out[ob2 + m] = a2[tn][m] * sc;
#pragma unroll
        for (int m = 4; m < 16; m++) out[ob2 + m] = 0.f;  // mm l=2,3 have no path
    }
}

// ---------------- launch 7: main skip TP, NT=4, z-paired tt + m-paired a1 ----------------
__global__ void __launch_bounds__(128) k_skip(const float* __restrict__ na,
                                              float* __restrict__ out)
{
    __shared__ float s_ml[4][2048];
    int v = threadIdx.x;
    int n0 = blockIdx.x * 4;

    for (int tn = 0; tn < 4; tn++) {
        const float4* src = reinterpret_cast<const float4*>(&g_msglin[(size_t)(n0 + tn) * 2048]);
        float4* dst = reinterpret_cast<float4*>(s_ml[tn]);
        for (int i = v; i < 512; i += 128) dst[i] = src[i];
    }
    float2 at2[4][5];
#pragma unroll
    for (int tn = 0; tn < 4; tn++)
#pragma unroll
        for (int k = 0; k < 5; k++)
            at2[tn][k] = f2(__ldg(&na[(n0 + tn) * 10 + 2 * k]),
                            __ldg(&na[(n0 + tn) * 10 + 2 * k + 1]));
    __syncthreads();

    float2 a1p[4][8];
#pragma unroll
    for (int tn = 0; tn < 4; tn++)
#pragma unroll
        for (int k = 0; k < 8; k++) a1p[tn][k] = make_float2(0.f, 0.f);

    for (int uu = 0; uu < 128; uu++) {
        float tt[4][4];
#pragma unroll
        for (int l = 0; l < 4; l++) {
            const float2* W = &g_Wp[((l * 128 + uu) * 5) * 128 + v];
            float2 w0 = __ldg(W), w1 = __ldg(W + 128), w2 = __ldg(W + 256);
            float2 w3 = __ldg(W + 384), w4 = __ldg(W + 512);
#pragma unroll
            for (int tn = 0; tn < 4; tn++) {
                float2 s = make_float2(0.f, 0.f);
                s = ffma2(at2[tn][0], w0, s);
                s = ffma2(at2[tn][1], w1, s);
                s = ffma2(at2[tn][2], w2, s);
                s = ffma2(at2[tn][3], w3, s);
                s = ffma2(at2[tn][4], w4, s);
                tt[tn][l] = s.x + s.y;
            }
        }
#pragma unroll
        for (int tn = 0; tn < 4; tn++) {
            float2 t01 = f2(tt[tn][0], tt[tn][1]);
            float2 t11 = make2(tt[tn][1]);
            float2 t22 = make2(tt[tn][2]);
            float2 t23 = f2(tt[tn][2], tt[tn][3]);
            float2 t33 = make2(tt[tn][3]);
            const float4* mp = reinterpret_cast<const float4*>(&s_ml[tn][uu * 16]);
            float4 c0 = mp[0], c1 = mp[1], c2 = mp[2], c3 = mp[3];
            a1p[tn][0] = ffma2(f2(c0.x, c0.y), t01, a1p[tn][0]);
            a1p[tn][1] = ffma2(f2(c0.z, c0.w), t11, a1p[tn][1]);
            a1p[tn][2] = ffma2(f2(c1.x, c1.y), t22, a1p[tn][2]);
            a1p[tn][3] = ffma2(f2(c1.z, c1.w), t22, a1p[tn][3]);
            a1p[tn][4] = ffma2(f2(c2.x, c2.y), t23, a1p[tn][4]);
            a1p[tn][5] = ffma2(f2(c2.z, c2.w), t33, a1p[tn][5]);
            a1p[tn][6] = ffma2(f2(c3.x, c3.y), t33, a1p[tn][6]);
            a1p[tn][7] = ffma2(f2(c3.z, c3.w), t33, a1p[tn][7]);
        }
    }
    const float sc = 0.02795084971874737f;  // 1/sqrt(1280)
#pragma unroll
    for (int tn = 0; tn < 4; tn++) {
        size_t ob = ((size_t)(n0 + tn) * 128 + v) * 16;
#pragma unroll
        for (int k = 0; k < 8; k++) {
            out[ob + 2 * k]     = a1p[tn][k].x * sc;
            out[ob + 2 * k + 1] = a1p[tn][k].y * sc;
        }
    }
}

// ---------------- host ----------------
extern "C" void kernel_launch(void* const* d_in, const int* in_sizes, int n_in,
                              void* d_out, int out_size)
{
    const int* ei;
    int wi;
    if (in_sizes[6] == 2 * NE) { ei = (const int*)d_in[6]; wi = 7; }
    else                       { ei = (const int*)d_in[n_in - 1]; wi = 6; }

    const float* na   = (const float*)d_in[0];
    const float* nf   = (const float*)d_in[1];
    const float* ea   = (const float*)d_in[2];
    const float* ef   = (const float*)d_in[3];
    const float* mmi  = (const float*)d_in[4];
    const float* mma  = (const float*)d_in[5];
    const float* Wup  = (const float*)d_in[wi + 0];
    const float* W1   = (const float*)d_in[wi + 1];
    const float* W2   = (const float*)d_in[wi + 2];
    const float* W3   = (const float*)d_in[wi + 3];
    const float* W4   = (const float*)d_in[wi + 4];
    const float* M1   = (const float*)d_in[wi + 5];
    const float* M2   = (const float*)d_in[wi + 6];
    const float* M3   = (const float*)d_in[wi + 7];
    const float* M4   = (const float*)d_in[wi + 8];
    const float* Wd   = (const float*)d_in[wi + 9];
    const float* Wlin = (const float*)d_in[wi + 10];
    const float* Wmlin= (const float*)d_in[wi + 11];
    const float* Wsk  = (const float*)d_in[wi + 12];
    const float* Wmsk = (const float*)d_in[wi + 13];
    float* out = (float*)d_out;

    k_hx<<<NN, 128>>>(nf, Wup, ei, Wsk, Wmsk);                    // 1: x + hist + weight pack
    k_scanmeff<<<1, 1024>>>(M1, M2, M3, M4);                      // 2
    k_scatter<<<(NE + 255) / 256, 256>>>(ei);                     // 3
    k_edge<<<NE / 8, 256>>>(W1, W2, W3, W4, ea, ef, mmi, mma, Wd, ei);  // 4 <- ncu slot
    k_agg<<<NN / 4, 128>>>(ea, Wlin, Wmlin);                      // 5
    k_skipmm<<<NN / 8, 128>>>(na, out);                           // 6
    k_skip<<<NN / 4, 128>>>(na, out);                             // 7
}